// round 12
// baseline (speedup 1.0000x reference)
#include <cuda_runtime.h>
#include <cuda_fp16.h>
#include <math.h>
#include <cstdint>

#define NN 100000
#define EE 300000
#define IN_DIM 10
#define HID 384
#define TT 5
#define BN_EPS 1e-5f
#define WMAT (HID * HID)

#define SCAN_B 1024
#define NSCANB ((NN + SCAN_B - 1) / SCAN_B)   // 98

// Static scratch (allocation-free rule) — all activations fp16
__device__ __half  g_shA [(size_t)NN * HID];
__device__ __half  g_shB [(size_t)NN * HID];
__device__ float   g_agg10[(size_t)NN * IN_DIM];
__device__ __half  g_wl16[4 * WMAT];
__device__ __half  g_wr16[4 * WMAT];
__device__ __half  g_wp016[WMAT];
__device__ __half  g_wp116[WMAT];
__device__ int   g_deg [NN];
__device__ int   g_inc [NN];
__device__ int   g_rowptr[NN + 1];
__device__ int   g_cur [NN];
__device__ int   g_csrc[EE];
__device__ int   g_bsum[128];

// ---------------------------------------------------------------------------
// helpers
// ---------------------------------------------------------------------------
__device__ __forceinline__ uint32_t smem_u32(const void* p) {
    uint32_t a;
    asm("{ .reg .u64 t; cvta.to.shared.u64 t, %1; cvt.u32.u64 %0, t; }" : "=r"(a) : "l"(p));
    return a;
}

__device__ __forceinline__ void mma_f16(float* c, uint32_t a0, uint32_t a1,
                                        uint32_t a2, uint32_t a3,
                                        uint32_t b0, uint32_t b1) {
    asm volatile("mma.sync.aligned.m16n8k16.row.col.f32.f16.f16.f32 "
                 "{%0,%1,%2,%3}, {%4,%5,%6,%7}, {%8,%9}, {%0,%1,%2,%3};"
                 : "+f"(c[0]), "+f"(c[1]), "+f"(c[2]), "+f"(c[3])
                 : "r"(a0), "r"(a1), "r"(a2), "r"(a3), "r"(b0), "r"(b1));
}

#define LDSM_X4(r0, r1, r2, r3, addr) \
    asm volatile("ldmatrix.sync.aligned.m8n8.x4.shared.b16 {%0,%1,%2,%3}, [%4];" \
                 : "=r"(r0), "=r"(r1), "=r"(r2), "=r"(r3) : "r"(addr))

__device__ __forceinline__ float elu_f(float v) {
    return (v > 0.0f) ? v : (__expf(v) - 1.0f);
}

__device__ __forceinline__ uint32_t h2pack(float x, float y) {
    __half2 h = __float22half2_rn(make_float2(x, y));
    return *(uint32_t*)&h;
}

// fp32 -> fp16 weight conversion (vectorized)
__global__ void k_cvt4(const float4* __restrict__ src, uint2* __restrict__ dst, int n4) {
    int i = blockIdx.x * blockDim.x + threadIdx.x;
    if (i >= n4) return;
    float4 v = src[i];
    uint2 o;
    o.x = h2pack(v.x, v.y);
    o.y = h2pack(v.z, v.w);
    dst[i] = o;
}

// ---------------------------------------------------------------------------
// CSR build
// ---------------------------------------------------------------------------
__global__ void k_hist(const int* __restrict__ dst, int* __restrict__ deg, int e) {
    int i = blockIdx.x * blockDim.x + threadIdx.x;
    if (i < e) atomicAdd(&deg[dst[i]], 1);
}

__global__ void k_scan_block(const int* __restrict__ deg, int* __restrict__ inc,
                             int* __restrict__ bsum, int n) {
    __shared__ int s[SCAN_B];
    int i = blockIdx.x * SCAN_B + threadIdx.x;
    s[threadIdx.x] = (i < n) ? deg[i] : 0;
    __syncthreads();
#pragma unroll
    for (int o = 1; o < SCAN_B; o <<= 1) {
        int t = (threadIdx.x >= o) ? s[threadIdx.x - o] : 0;
        __syncthreads();
        s[threadIdx.x] += t;
        __syncthreads();
    }
    if (i < n) inc[i] = s[threadIdx.x];
    if (threadIdx.x == SCAN_B - 1) bsum[blockIdx.x] = s[SCAN_B - 1];
}

__global__ void k_scan_bsum(int* __restrict__ bsum, int nb) {
    __shared__ int s[128];
    if (threadIdx.x < nb) s[threadIdx.x] = bsum[threadIdx.x];
    __syncthreads();
    if (threadIdx.x == 0) {
        int run = 0;
        for (int i = 0; i < nb; i++) { run += s[i]; s[i] = run; }
    }
    __syncthreads();
    if (threadIdx.x < nb) bsum[threadIdx.x] = s[threadIdx.x];
}

__global__ void k_csr_fin(const int* __restrict__ deg, const int* __restrict__ inc,
                          const int* __restrict__ bsum,
                          int* __restrict__ rowptr, int* __restrict__ cur, int n) {
    int i = blockIdx.x * blockDim.x + threadIdx.x;
    if (i >= n) return;
    int b = i / SCAN_B;
    int total = inc[i] + (b > 0 ? bsum[b - 1] : 0);
    rowptr[i + 1] = total;
    cur[i] = total - deg[i];
    if (i == 0) rowptr[0] = 0;
}

__global__ void k_fill(const int* __restrict__ src, const int* __restrict__ dst,
                       int* __restrict__ cur, int* __restrict__ csrc, int e) {
    int i = blockIdx.x * blockDim.x + threadIdx.x;
    if (i >= e) return;
    int pos = atomicAdd(&cur[dst[i]], 1);
    csrc[pos] = src[i];
}

// width 10: thread per (node, feature), fp32 source
__global__ void k_gather10(const int* __restrict__ rowptr, const int* __restrict__ csrc,
                           const float* __restrict__ x, float* __restrict__ agg, int n) {
    int idx = blockIdx.x * blockDim.x + threadIdx.x;
    if (idx >= n * IN_DIM) return;
    int node = idx / IN_DIM, f = idx % IN_DIM;
    int beg = rowptr[node], end = rowptr[node + 1];
    float a = 0.0f;
    for (int e = beg; e < end; e++)
        a += x[(size_t)csrc[e] * IN_DIM + f];
    agg[idx] = a / fmaxf((float)(end - beg), 1.0f);
}

// ---------------------------------------------------------------------------
// Layer 0 SAGE: K=10, 32 rows/block, 384 threads; writes fp16 only
// ---------------------------------------------------------------------------
#define L0R 32
__global__ void k_layer0(const float* __restrict__ agg, const float* __restrict__ x,
                         const float* __restrict__ Wl, const float* __restrict__ bl,
                         const float* __restrict__ Wr,
                         const float* __restrict__ bng, const float* __restrict__ bnb,
                         const float* __restrict__ bnm, const float* __restrict__ bnv,
                         __half* __restrict__ hs, int n) {
    __shared__ float sA[L0R][IN_DIM];
    __shared__ float sX[L0R][IN_DIM];
    __shared__ float red[L0R];
    int t = threadIdx.x;
    int row0 = blockIdx.x * L0R;

    if (t < L0R * IN_DIM) {
        int r = t / IN_DIM, k = t % IN_DIM;
        int row = row0 + r;
        sA[r][k] = (row < n) ? agg[(size_t)row * IN_DIM + k] : 0.0f;
        sX[r][k] = (row < n) ? x[(size_t)row * IN_DIM + k] : 0.0f;
    } else if (t < L0R * IN_DIM + L0R) {
        red[t - L0R * IN_DIM] = 0.0f;
    }
    __syncthreads();

    int j = t;
    float wl[IN_DIM], wr[IN_DIM];
#pragma unroll
    for (int k = 0; k < IN_DIM; k++) {
        wl[k] = Wl[j * IN_DIM + k];
        wr[k] = Wr[j * IN_DIM + k];
    }
    float bb = bl[j];

    float v[L0R];
#pragma unroll
    for (int r = 0; r < L0R; r++) {
        float s = bb;
#pragma unroll
        for (int k = 0; k < IN_DIM; k++)
            s += sA[r][k] * wl[k] + sX[r][k] * wr[k];
        v[r] = s;
    }

    int lane = t & 31;
#pragma unroll
    for (int r = 0; r < L0R; r++) {
        float p = v[r] * v[r];
#pragma unroll
        for (int o = 16; o > 0; o >>= 1) p += __shfl_xor_sync(0xFFFFFFFFu, p, o);
        if (lane == 0) atomicAdd(&red[r], p);
    }
    __syncthreads();

    float gm = bng[j], gb = bnb[j], mm = bnm[j], vv = bnv[j];
    float bscale = rsqrtf(vv + BN_EPS) * gm;
#pragma unroll
    for (int r = 0; r < L0R; r++) {
        int row = row0 + r;
        if (row >= n) continue;
        float sc = 1.0f / fmaxf(sqrtf(red[r]), 1e-12f);
        float val = elu_f((v[r] * sc - mm) * bscale + gb);
        hs[(size_t)row * HID + j] = __float2half(val);
    }
}

// ---------------------------------------------------------------------------
// fp16 mma.sync fused GEMM with in-kernel CSR gather + persistent A tiles.
//   dual (W2 != null): At1 = mean-gather of neighbors (from hsrc via CSR),
//                      At2 = own rows of hsrc;  C = At1*W1^T + At2*W2^T + bias
//   plain: At1 = rows of A1 input;  C = At1*W1^T + bias
// Main loop stages W only (double-buffered, 1 bar/iter); A via ldmatrix from
// persistent tiles (row stride 392 halves = 784B, conflict-free).
//   epi 0: L2-normalize row, BN, ELU -> fp16 out
//   epi 1: BN, ReLU -> fp16 out
//   epi 2: BN, ReLU, then outf = h @ Wp2^T + bp2 (writes [N,3] fp32)
// ---------------------------------------------------------------------------
#define HSTR 24
#define ASTR2 392
#define AT_HALVES (64 * ASTR2)          // 25088
#define WBUF (384 * HSTR)               // 9216
#define DSMEM_HALVES (2 * AT_HALVES + 2 * WBUF)   // 68608
#define DSMEM_BYTES (DSMEM_HALVES * 2)            // 137216

__global__ void __launch_bounds__(512, 1)
k_mma(const int* __restrict__ rowptr, const int* __restrict__ csrc,
      const __half* __restrict__ hsrc,          // dual: gather source + own rows
      const __half* __restrict__ A1,            // plain: direct A
      const __half* __restrict__ W1, const float* __restrict__ bias,
      const __half* __restrict__ W2,            // null -> plain
      const float* __restrict__ bng, const float* __restrict__ bnb,
      const float* __restrict__ bnm, const float* __restrict__ bnv,
      __half* __restrict__ outh, float* __restrict__ outf,
      int nrows, int epi,
      const float* __restrict__ Wp2, const float* __restrict__ bp2) {
    extern __shared__ __half smh[];
    __half* At1  = smh;
    __half* At2  = smh + AT_HALVES;
    __half* WsB0 = smh + 2 * AT_HALVES;
    __half* WsB1 = smh + 2 * AT_HALVES + WBUF;

    __shared__ float sSB[HID], sS2[HID], sAD[HID];
    __shared__ float sWp[3 * HID];
    __shared__ float red[64];
    __shared__ float redF[192];

    const int tid  = threadIdx.x;
    const int lane = tid & 31;
    const int wid  = tid >> 5;
    const int rw   = wid & 1;
    const int cw   = wid >> 1;
    const int g    = lane >> 2;
    const int t4   = lane & 3;
    const int warpRow = rw * 32;
    const int cb   = cw * 48;
    const int rb   = blockIdx.x * 64;
    const bool dual = (W2 != nullptr);

    for (int c = tid; c < HID; c += 512) {
        float s2 = rsqrtf(bnv[c] + BN_EPS) * bng[c];
        sSB[c] = bias[c];
        sS2[c] = s2;
        sAD[c] = bnb[c] - bnm[c] * s2;
    }
    if (tid < 64) red[tid] = 0.0f;
    if (tid < 192) redF[tid] = 0.0f;
    if (epi == 2)
        for (int c = tid; c < 3 * HID; c += 512) sWp[c] = Wp2[c];

    // ---- build persistent A tiles ----
    if (dual) {
        // each warp: 4 nodes; gather mean into At1, copy own row into At2
        for (int q = 0; q < 4; q++) {
            int r = wid * 4 + q;
            int node = rb + r;
            uint32_t boff = r * ASTR2 + lane * 4;
            if (node < nrows) {
                int beg = rowptr[node], end = rowptr[node + 1];
                float a[12], b[12];
#pragma unroll
                for (int i = 0; i < 12; i++) { a[i] = 0.0f; b[i] = 0.0f; }
                int e = beg;
                for (; e + 1 < end; e += 2) {
                    int s0 = csrc[e], s1 = csrc[e + 1];
                    const uint2* p0 = (const uint2*)(hsrc + (size_t)s0 * HID) + lane;
                    const uint2* p1 = (const uint2*)(hsrc + (size_t)s1 * HID) + lane;
                    uint2 u0 = p0[0], u1 = p0[32], u2 = p0[64];
                    uint2 w0 = p1[0], w1 = p1[32], w2 = p1[64];
                    float2 f;
                    f = __half22float2(*(__half2*)&u0.x); a[0] += f.x; a[1] += f.y;
                    f = __half22float2(*(__half2*)&u0.y); a[2] += f.x; a[3] += f.y;
                    f = __half22float2(*(__half2*)&u1.x); a[4] += f.x; a[5] += f.y;
                    f = __half22float2(*(__half2*)&u1.y); a[6] += f.x; a[7] += f.y;
                    f = __half22float2(*(__half2*)&u2.x); a[8] += f.x; a[9] += f.y;
                    f = __half22float2(*(__half2*)&u2.y); a[10] += f.x; a[11] += f.y;
                    f = __half22float2(*(__half2*)&w0.x); b[0] += f.x; b[1] += f.y;
                    f = __half22float2(*(__half2*)&w0.y); b[2] += f.x; b[3] += f.y;
                    f = __half22float2(*(__half2*)&w1.x); b[4] += f.x; b[5] += f.y;
                    f = __half22float2(*(__half2*)&w1.y); b[6] += f.x; b[7] += f.y;
                    f = __half22float2(*(__half2*)&w2.x); b[8] += f.x; b[9] += f.y;
                    f = __half22float2(*(__half2*)&w2.y); b[10] += f.x; b[11] += f.y;
                }
                if (e < end) {
                    const uint2* p0 = (const uint2*)(hsrc + (size_t)csrc[e] * HID) + lane;
                    uint2 u0 = p0[0], u1 = p0[32], u2 = p0[64];
                    float2 f;
                    f = __half22float2(*(__half2*)&u0.x); a[0] += f.x; a[1] += f.y;
                    f = __half22float2(*(__half2*)&u0.y); a[2] += f.x; a[3] += f.y;
                    f = __half22float2(*(__half2*)&u1.x); a[4] += f.x; a[5] += f.y;
                    f = __half22float2(*(__half2*)&u1.y); a[6] += f.x; a[7] += f.y;
                    f = __half22float2(*(__half2*)&u2.x); a[8] += f.x; a[9] += f.y;
                    f = __half22float2(*(__half2*)&u2.y); a[10] += f.x; a[11] += f.y;
                }
                float iv = 1.0f / fmaxf((float)(end - beg), 1.0f);
                uint2 r0, r1, r2;
                r0.x = h2pack((a[0]+b[0])*iv, (a[1]+b[1])*iv);
                r0.y = h2pack((a[2]+b[2])*iv, (a[3]+b[3])*iv);
                r1.x = h2pack((a[4]+b[4])*iv, (a[5]+b[5])*iv);
                r1.y = h2pack((a[6]+b[6])*iv, (a[7]+b[7])*iv);
                r2.x = h2pack((a[8]+b[8])*iv, (a[9]+b[9])*iv);
                r2.y = h2pack((a[10]+b[10])*iv, (a[11]+b[11])*iv);
                *(uint2*)&At1[boff]       = r0;
                *(uint2*)&At1[boff + 128] = r1;
                *(uint2*)&At1[boff + 256] = r2;
                // own row
                const uint2* p = (const uint2*)(hsrc + (size_t)node * HID) + lane;
                *(uint2*)&At2[boff]       = p[0];
                *(uint2*)&At2[boff + 128] = p[32];
                *(uint2*)&At2[boff + 256] = p[64];
            } else {
                uint2 z = make_uint2(0u, 0u);
                *(uint2*)&At1[boff] = z; *(uint2*)&At1[boff + 128] = z; *(uint2*)&At1[boff + 256] = z;
                *(uint2*)&At2[boff] = z; *(uint2*)&At2[boff + 128] = z; *(uint2*)&At2[boff + 256] = z;
            }
        }
    } else {
        // plain copy: 64 rows x 96 uint2
#pragma unroll
        for (int j = 0; j < 12; j++) {
            int idx = tid + j * 512;
            int r = idx / 96, c = idx % 96;
            uint2 v = make_uint2(0u, 0u);
            if (rb + r < nrows)
                v = *(const uint2*)(A1 + (size_t)(rb + r) * HID + c * 4);
            *(uint2*)&At1[r * ASTR2 + c * 4] = v;
        }
    }

    // ldmatrix A base addresses (per pass, per m-tile); per-iter add chunk*32B
    const int m8 = lane >> 3;
    const int r8 = lane & 7;
    uint32_t aBase[2][2], bAddr[2][3];
    {
        int rowi = (m8 & 1) * 8 + r8;
        int koffq = (m8 >> 1) * 8;
        int nrowi = (m8 >> 1) * 8 + r8;
        int nkoff = (m8 & 1) * 8;
#pragma unroll
        for (int mt = 0; mt < 2; mt++) {
            int off = (warpRow + mt * 16 + rowi) * ASTR2 + koffq;
            aBase[0][mt] = smem_u32(&At1[off]);
            aBase[1][mt] = smem_u32(&At2[off]);
        }
#pragma unroll
        for (int p = 0; p < 3; p++) {
            int off = (cb + p * 16 + nrowi) * HSTR + nkoff;
            bAddr[0][p] = smem_u32(&WsB0[off]);
            bAddr[1][p] = smem_u32(&WsB1[off]);
        }
    }

    int wr_[3], wq_[3], wOff[3];
#pragma unroll
    for (int i = 0; i < 3; i++) {
        int idx = tid + i * 512;
        wr_[i] = idx >> 2;
        wq_[i] = idx & 3;
        wOff[i] = wr_[i] * HSTR + wq_[i] * 4;
    }

    const int S = dual ? 48 : 24;

    float acc[2][6][4];
#pragma unroll
    for (int mt = 0; mt < 2; mt++)
#pragma unroll
        for (int nt = 0; nt < 6; nt++)
#pragma unroll
            for (int q = 0; q < 4; q++) acc[mt][nt][q] = 0.0f;

    uint2 wvP[3];
    // prologue: stage W chunk 0 into buf 0
#pragma unroll
    for (int i = 0; i < 3; i++) {
        wvP[i] = *(const uint2*)(W1 + (size_t)wr_[i] * HID + wq_[i] * 4);
        *(uint2*)&WsB0[wOff[i]] = wvP[i];
    }

    for (int it = 0; it < S; it++) {
        const int b = it & 1;
        __syncthreads();   // A tiles + W buf b stores now visible

        // prefetch W chunk it+1
        if (it + 1 < S) {
            const int itn = it + 1;
            const int pass = itn / 24;
            const int k0 = (itn - pass * 24) * 16;
            const __half* W = pass ? W2 : W1;
#pragma unroll
            for (int i = 0; i < 3; i++)
                wvP[i] = *(const uint2*)(W + (size_t)wr_[i] * HID + k0 + wq_[i] * 4);
        }

        // compute from persistent A tile (pass) + W buf b
        {
            const int pass = it / 24;
            const uint32_t ko = (uint32_t)((it - pass * 24) * 32);  // bytes
            uint32_t a[2][4];
            LDSM_X4(a[0][0], a[0][1], a[0][2], a[0][3], aBase[pass][0] + ko);
            LDSM_X4(a[1][0], a[1][1], a[1][2], a[1][3], aBase[pass][1] + ko);
            uint32_t bfr[12];
            LDSM_X4(bfr[0], bfr[1], bfr[2],  bfr[3],  bAddr[b][0]);
            LDSM_X4(bfr[4], bfr[5], bfr[6],  bfr[7],  bAddr[b][1]);
            LDSM_X4(bfr[8], bfr[9], bfr[10], bfr[11], bAddr[b][2]);
#pragma unroll
            for (int nt = 0; nt < 6; nt++) {
                uint32_t b0 = bfr[nt * 2], b1 = bfr[nt * 2 + 1];
                mma_f16(acc[0][nt], a[0][0], a[0][1], a[0][2], a[0][3], b0, b1);
                mma_f16(acc[1][nt], a[1][0], a[1][1], a[1][2], a[1][3], b0, b1);
            }
        }

        // stage W chunk it+1 into the other buffer
        if (it + 1 < S) {
            __half* Wn = b ? WsB0 : WsB1;
#pragma unroll
            for (int i = 0; i < 3; i++)
                *(uint2*)&Wn[wOff[i]] = wvP[i];
        }
    }
    __syncthreads();

    // ---- epilogue ----
#pragma unroll
    for (int nt = 0; nt < 6; nt++) {
        int col = cb + nt * 8 + 2 * t4;
        float b0 = sSB[col], b1 = sSB[col + 1];
#pragma unroll
        for (int mt = 0; mt < 2; mt++) {
            acc[mt][nt][0] += b0; acc[mt][nt][1] += b1;
            acc[mt][nt][2] += b0; acc[mt][nt][3] += b1;
        }
    }

    float sc0[2] = {1.0f, 1.0f}, sc1[2] = {1.0f, 1.0f};
    if (epi == 0) {
#pragma unroll
        for (int mt = 0; mt < 2; mt++) {
            float s0 = 0.0f, s1 = 0.0f;
#pragma unroll
            for (int nt = 0; nt < 6; nt++) {
                s0 = fmaf(acc[mt][nt][0], acc[mt][nt][0], s0);
                s0 = fmaf(acc[mt][nt][1], acc[mt][nt][1], s0);
                s1 = fmaf(acc[mt][nt][2], acc[mt][nt][2], s1);
                s1 = fmaf(acc[mt][nt][3], acc[mt][nt][3], s1);
            }
            s0 += __shfl_xor_sync(0xFFFFFFFFu, s0, 1);
            s0 += __shfl_xor_sync(0xFFFFFFFFu, s0, 2);
            s1 += __shfl_xor_sync(0xFFFFFFFFu, s1, 1);
            s1 += __shfl_xor_sync(0xFFFFFFFFu, s1, 2);
            if (t4 == 0) {
                atomicAdd(&red[warpRow + mt * 16 + g], s0);
                atomicAdd(&red[warpRow + mt * 16 + g + 8], s1);
            }
        }
        __syncthreads();
#pragma unroll
        for (int mt = 0; mt < 2; mt++) {
            sc0[mt] = 1.0f / fmaxf(sqrtf(red[warpRow + mt * 16 + g]), 1e-12f);
            sc1[mt] = 1.0f / fmaxf(sqrtf(red[warpRow + mt * 16 + g + 8]), 1e-12f);
        }
    }

    if (epi == 2) {
        float p0[2][3], p1[2][3];
#pragma unroll
        for (int mt = 0; mt < 2; mt++)
#pragma unroll
            for (int o = 0; o < 3; o++) { p0[mt][o] = 0.0f; p1[mt][o] = 0.0f; }

#pragma unroll
        for (int mt = 0; mt < 2; mt++) {
#pragma unroll
            for (int nt = 0; nt < 6; nt++) {
                int col = cb + nt * 8 + 2 * t4;
                float m0 = sS2[col], m1 = sS2[col + 1];
                float d0 = sAD[col], d1 = sAD[col + 1];
                float x0 = fmaxf(acc[mt][nt][0] * m0 + d0, 0.0f);
                float x1 = fmaxf(acc[mt][nt][1] * m1 + d1, 0.0f);
                float x2 = fmaxf(acc[mt][nt][2] * m0 + d0, 0.0f);
                float x3 = fmaxf(acc[mt][nt][3] * m1 + d1, 0.0f);
#pragma unroll
                for (int o = 0; o < 3; o++) {
                    float w0 = sWp[o * HID + col], w1 = sWp[o * HID + col + 1];
                    p0[mt][o] = fmaf(x0, w0, fmaf(x1, w1, p0[mt][o]));
                    p1[mt][o] = fmaf(x2, w0, fmaf(x3, w1, p1[mt][o]));
                }
            }
        }
#pragma unroll
        for (int mt = 0; mt < 2; mt++)
#pragma unroll
            for (int o = 0; o < 3; o++) {
                float v0 = p0[mt][o], v1 = p1[mt][o];
                v0 += __shfl_xor_sync(0xFFFFFFFFu, v0, 1);
                v0 += __shfl_xor_sync(0xFFFFFFFFu, v0, 2);
                v1 += __shfl_xor_sync(0xFFFFFFFFu, v1, 1);
                v1 += __shfl_xor_sync(0xFFFFFFFFu, v1, 2);
                if (t4 == 0) {
                    atomicAdd(&redF[(warpRow + mt * 16 + g) * 3 + o], v0);
                    atomicAdd(&redF[(warpRow + mt * 16 + g + 8) * 3 + o], v1);
                }
            }
        __syncthreads();
        if (tid < 64) {
            int row = rb + tid;
            if (row < nrows) {
                outf[(size_t)row * 3 + 0] = redF[tid * 3 + 0] + bp2[0];
                outf[(size_t)row * 3 + 1] = redF[tid * 3 + 1] + bp2[1];
                outf[(size_t)row * 3 + 2] = redF[tid * 3 + 2] + bp2[2];
            }
        }
        return;
    }

#pragma unroll
    for (int mt = 0; mt < 2; mt++) {
        int row0 = rb + warpRow + mt * 16 + g;
        int row1 = row0 + 8;
        bool v0r = (row0 < nrows), v1r = (row1 < nrows);
#pragma unroll
        for (int nt = 0; nt < 6; nt++) {
            int col = cb + nt * 8 + 2 * t4;
            float m0 = sS2[col], m1 = sS2[col + 1];
            float d0 = sAD[col], d1 = sAD[col + 1];
            float x0 = acc[mt][nt][0] * sc0[mt] * m0 + d0;
            float x1 = acc[mt][nt][1] * sc0[mt] * m1 + d1;
            float x2 = acc[mt][nt][2] * sc1[mt] * m0 + d0;
            float x3 = acc[mt][nt][3] * sc1[mt] * m1 + d1;
            if (epi == 0) {
                x0 = elu_f(x0); x1 = elu_f(x1);
                x2 = elu_f(x2); x3 = elu_f(x3);
            } else {
                x0 = fmaxf(x0, 0.0f); x1 = fmaxf(x1, 0.0f);
                x2 = fmaxf(x2, 0.0f); x3 = fmaxf(x3, 0.0f);
            }
            if (v0r) *(uint32_t*)(outh + (size_t)row0 * HID + col) = h2pack(x0, x1);
            if (v1r) *(uint32_t*)(outh + (size_t)row1 * HID + col) = h2pack(x2, x3);
        }
    }
}

// ---------------------------------------------------------------------------
extern "C" void kernel_launch(void* const* d_in, const int* in_sizes, int n_in,
                              void* d_out, int out_size) {
    const float* x    = (const float*)d_in[0];
    const int*   ei   = (const int*)  d_in[1];
    const float* Wl0  = (const float*)d_in[2];
    const float* bl0  = (const float*)d_in[3];
    const float* Wr0  = (const float*)d_in[4];
    const float* Wl   = (const float*)d_in[5];
    const float* bl   = (const float*)d_in[6];
    const float* Wr   = (const float*)d_in[7];
    const float* bng  = (const float*)d_in[8];
    const float* bnb  = (const float*)d_in[9];
    const float* bnm  = (const float*)d_in[10];
    const float* bnv  = (const float*)d_in[11];
    const float* Wp0  = (const float*)d_in[12];
    const float* bp0  = (const float*)d_in[13];
    const float* Wp1  = (const float*)d_in[14];
    const float* bp1  = (const float*)d_in[15];
    const float* Wp2  = (const float*)d_in[16];
    const float* bp2  = (const float*)d_in[17];
    const float* pg   = (const float*)d_in[18];
    const float* pb   = (const float*)d_in[19];
    const float* pm   = (const float*)d_in[20];
    const float* pv   = (const float*)d_in[21];

    const int* src = ei;
    const int* dst = ei + EE;

    __half *shA, *shB, *wl16, *wr16, *wp016, *wp116;
    float *agg10;
    int *deg, *inc, *rowptr, *cur, *csrc, *bsum;
    cudaGetSymbolAddress((void**)&shA,    g_shA);
    cudaGetSymbolAddress((void**)&shB,    g_shB);
    cudaGetSymbolAddress((void**)&agg10,  g_agg10);
    cudaGetSymbolAddress((void**)&wl16,   g_wl16);
    cudaGetSymbolAddress((void**)&wr16,   g_wr16);
    cudaGetSymbolAddress((void**)&wp016,  g_wp016);
    cudaGetSymbolAddress((void**)&wp116,  g_wp116);
    cudaGetSymbolAddress((void**)&deg,    g_deg);
    cudaGetSymbolAddress((void**)&inc,    g_inc);
    cudaGetSymbolAddress((void**)&rowptr, g_rowptr);
    cudaGetSymbolAddress((void**)&cur,    g_cur);
    cudaGetSymbolAddress((void**)&csrc,   g_csrc);
    cudaGetSymbolAddress((void**)&bsum,   g_bsum);

    cudaFuncSetAttribute(k_mma, cudaFuncAttributeMaxDynamicSharedMemorySize, DSMEM_BYTES);

    // ---- weight conversion (fp32 -> fp16), once per call ----
    {
        int n4 = 4 * WMAT / 4;
        k_cvt4<<<(n4 + 255) / 256, 256>>>((const float4*)Wl, (uint2*)wl16, n4);
        k_cvt4<<<(n4 + 255) / 256, 256>>>((const float4*)Wr, (uint2*)wr16, n4);
        int p4 = WMAT / 4;
        k_cvt4<<<(p4 + 255) / 256, 256>>>((const float4*)Wp0, (uint2*)wp016, p4);
        k_cvt4<<<(p4 + 255) / 256, 256>>>((const float4*)Wp1, (uint2*)wp116, p4);
    }

    // ---- CSR build ----
    cudaMemsetAsync(deg, 0, NN * sizeof(int));
    k_hist<<<(EE + 255) / 256, 256>>>(dst, deg, EE);
    k_scan_block<<<NSCANB, SCAN_B>>>(deg, inc, bsum, NN);
    k_scan_bsum<<<1, 128>>>(bsum, NSCANB);
    k_csr_fin<<<(NN + 255) / 256, 256>>>(deg, inc, bsum, rowptr, cur, NN);
    k_fill<<<(EE + 255) / 256, 256>>>(src, dst, cur, csrc, EE);

    // ---- layer 0 (K=10) ----
    k_gather10<<<(NN * IN_DIM + 255) / 256, 256>>>(rowptr, csrc, x, agg10, NN);
    k_layer0<<<(NN + L0R - 1) / L0R, 384>>>(agg10, x, Wl0, bl0, Wr0,
                                            bng, bnb, bnm, bnv, shA, NN);

    // ---- layers 1..4: fused gather + dual fp16 mma GEMM ----
    const int gblocks = (NN + 63) / 64;
    for (int t = 1; t < TT; t++) {
        k_mma<<<gblocks, 512, DSMEM_BYTES>>>(
            rowptr, csrc, shA, nullptr,
            wl16 + (size_t)(t - 1) * WMAT, bl + (t - 1) * HID,
            wr16 + (size_t)(t - 1) * WMAT,
            bng + t * HID, bnb + t * HID, bnm + t * HID, bnv + t * HID,
            shB, nullptr, NN, 0, nullptr, nullptr);
        __half* ts = shA; shA = shB; shB = ts;
    }

    // ---- projection MLP (final [384->3] fused into second GEMM) ----
    k_mma<<<gblocks, 512, DSMEM_BYTES>>>(nullptr, nullptr, nullptr, shA,
                                         wp016, bp0, nullptr,
                                         pg, pb, pm, pv, shB, nullptr, NN, 1,
                                         nullptr, nullptr);
    k_mma<<<gblocks, 512, DSMEM_BYTES>>>(nullptr, nullptr, nullptr, shB,
                                         wp116, bp1, nullptr,
                                         pg + HID, pb + HID, pm + HID, pv + HID,
                                         nullptr, (float*)d_out, NN, 2,
                                         Wp2, bp2);

    (void)in_sizes; (void)n_in; (void)out_size;
}

// round 13
// speedup vs baseline: 1.0769x; 1.0769x over previous
#include <cuda_runtime.h>
#include <cuda_fp16.h>
#include <math.h>
#include <cstdint>

#define NN 100000
#define EE 300000
#define IN_DIM 10
#define HID 384
#define TT 5
#define BN_EPS 1e-5f
#define WMAT (HID * HID)

#define SCAN_B 1024
#define NSCANB ((NN + SCAN_B - 1) / SCAN_B)   // 98

// Static scratch (allocation-free rule) — all activations fp16
__device__ __half  g_agg16[(size_t)NN * HID];
__device__ __half  g_shA [(size_t)NN * HID];
__device__ __half  g_shB [(size_t)NN * HID];
__device__ float   g_agg10[(size_t)NN * IN_DIM];
__device__ __half  g_wl16[4 * WMAT];
__device__ __half  g_wr16[4 * WMAT];
__device__ __half  g_wp016[WMAT];
__device__ __half  g_wp116[WMAT];
__device__ int   g_deg [NN];
__device__ int   g_inc [NN];
__device__ int   g_rowptr[NN + 1];
__device__ int   g_cur [NN];
__device__ int   g_csrc[EE];
__device__ int   g_bsum[128];

// ---------------------------------------------------------------------------
// helpers
// ---------------------------------------------------------------------------
__device__ __forceinline__ uint32_t smem_u32(const void* p) {
    uint32_t a;
    asm("{ .reg .u64 t; cvta.to.shared.u64 t, %1; cvt.u32.u64 %0, t; }" : "=r"(a) : "l"(p));
    return a;
}

__device__ __forceinline__ void mma_f16(float* c, uint32_t a0, uint32_t a1,
                                        uint32_t a2, uint32_t a3,
                                        uint32_t b0, uint32_t b1) {
    asm volatile("mma.sync.aligned.m16n8k16.row.col.f32.f16.f16.f32 "
                 "{%0,%1,%2,%3}, {%4,%5,%6,%7}, {%8,%9}, {%0,%1,%2,%3};"
                 : "+f"(c[0]), "+f"(c[1]), "+f"(c[2]), "+f"(c[3])
                 : "r"(a0), "r"(a1), "r"(a2), "r"(a3), "r"(b0), "r"(b1));
}

#define LDSM_X4(r0, r1, r2, r3, addr) \
    asm volatile("ldmatrix.sync.aligned.m8n8.x4.shared.b16 {%0,%1,%2,%3}, [%4];" \
                 : "=r"(r0), "=r"(r1), "=r"(r2), "=r"(r3) : "r"(addr))

__device__ __forceinline__ float elu_f(float v) {
    return (v > 0.0f) ? v : (__expf(v) - 1.0f);
}

__device__ __forceinline__ uint32_t h2pack(float x, float y) {
    __half2 h = __float22half2_rn(make_float2(x, y));
    return *(uint32_t*)&h;
}

// single fp32->fp16 conversion kernel covering all weight arrays
__global__ void k_cvt_all(const float4* __restrict__ wl, const float4* __restrict__ wr,
                          const float4* __restrict__ wp0, const float4* __restrict__ wp1,
                          uint2* __restrict__ owl, uint2* __restrict__ owr,
                          uint2* __restrict__ owp0, uint2* __restrict__ owp1) {
    const int n1 = 4 * WMAT / 4;        // wl
    const int n2 = n1 + 4 * WMAT / 4;   // wr
    const int n3 = n2 + WMAT / 4;       // wp0
    const int n4 = n3 + WMAT / 4;       // wp1
    int i = blockIdx.x * blockDim.x + threadIdx.x;
    if (i >= n4) return;
    const float4* s;
    uint2* d;
    int j;
    if (i < n1)      { s = wl;  d = owl;  j = i; }
    else if (i < n2) { s = wr;  d = owr;  j = i - n1; }
    else if (i < n3) { s = wp0; d = owp0; j = i - n2; }
    else             { s = wp1; d = owp1; j = i - n3; }
    float4 v = s[j];
    uint2 o;
    o.x = h2pack(v.x, v.y);
    o.y = h2pack(v.z, v.w);
    d[j] = o;
}

// ---------------------------------------------------------------------------
// CSR build
// ---------------------------------------------------------------------------
__global__ void k_hist(const int* __restrict__ dst, int* __restrict__ deg, int e) {
    int i = blockIdx.x * blockDim.x + threadIdx.x;
    if (i < e) atomicAdd(&deg[dst[i]], 1);
}

__global__ void k_scan_block(const int* __restrict__ deg, int* __restrict__ inc,
                             int* __restrict__ bsum, int n) {
    __shared__ int s[SCAN_B];
    int i = blockIdx.x * SCAN_B + threadIdx.x;
    s[threadIdx.x] = (i < n) ? deg[i] : 0;
    __syncthreads();
#pragma unroll
    for (int o = 1; o < SCAN_B; o <<= 1) {
        int t = (threadIdx.x >= o) ? s[threadIdx.x - o] : 0;
        __syncthreads();
        s[threadIdx.x] += t;
        __syncthreads();
    }
    if (i < n) inc[i] = s[threadIdx.x];
    if (threadIdx.x == SCAN_B - 1) bsum[blockIdx.x] = s[SCAN_B - 1];
}

__global__ void k_scan_bsum(int* __restrict__ bsum, int nb) {
    __shared__ int s[128];
    if (threadIdx.x < nb) s[threadIdx.x] = bsum[threadIdx.x];
    __syncthreads();
    if (threadIdx.x == 0) {
        int run = 0;
        for (int i = 0; i < nb; i++) { run += s[i]; s[i] = run; }
    }
    __syncthreads();
    if (threadIdx.x < nb) bsum[threadIdx.x] = s[threadIdx.x];
}

__global__ void k_csr_fin(const int* __restrict__ deg, const int* __restrict__ inc,
                          const int* __restrict__ bsum,
                          int* __restrict__ rowptr, int* __restrict__ cur, int n) {
    int i = blockIdx.x * blockDim.x + threadIdx.x;
    if (i >= n) return;
    int b = i / SCAN_B;
    int total = inc[i] + (b > 0 ? bsum[b - 1] : 0);
    rowptr[i + 1] = total;
    cur[i] = total - deg[i];
    if (i == 0) rowptr[0] = 0;
}

__global__ void k_fill(const int* __restrict__ src, const int* __restrict__ dst,
                       int* __restrict__ cur, int* __restrict__ csrc, int e) {
    int i = blockIdx.x * blockDim.x + threadIdx.x;
    if (i >= e) return;
    int pos = atomicAdd(&cur[dst[i]], 1);
    csrc[pos] = src[i];
}

// ---------------------------------------------------------------------------
// CSR mean-gather, width 384, fp16 in/out, fp32 accumulate, 2x unroll
// ---------------------------------------------------------------------------
__global__ void k_gather384(const int* __restrict__ rowptr, const int* __restrict__ csrc,
                            const __half* __restrict__ hs, __half* __restrict__ agg,
                            int n) {
    int node = (blockIdx.x * blockDim.x + threadIdx.x) >> 5;
    int lane = threadIdx.x & 31;
    if (node >= n) return;
    int beg = rowptr[node], end = rowptr[node + 1];
    float a[12], b[12];
#pragma unroll
    for (int i = 0; i < 12; i++) { a[i] = 0.0f; b[i] = 0.0f; }

    int e = beg;
    for (; e + 1 < end; e += 2) {
        int s0 = csrc[e], s1 = csrc[e + 1];
        const uint2* p0 = (const uint2*)(hs + (size_t)s0 * HID) + lane;
        const uint2* p1 = (const uint2*)(hs + (size_t)s1 * HID) + lane;
        uint2 u0 = p0[0], u1 = p0[32], u2 = p0[64];
        uint2 w0 = p1[0], w1 = p1[32], w2 = p1[64];
        float2 f;
        f = __half22float2(*(__half2*)&u0.x); a[0] += f.x; a[1] += f.y;
        f = __half22float2(*(__half2*)&u0.y); a[2] += f.x; a[3] += f.y;
        f = __half22float2(*(__half2*)&u1.x); a[4] += f.x; a[5] += f.y;
        f = __half22float2(*(__half2*)&u1.y); a[6] += f.x; a[7] += f.y;
        f = __half22float2(*(__half2*)&u2.x); a[8] += f.x; a[9] += f.y;
        f = __half22float2(*(__half2*)&u2.y); a[10] += f.x; a[11] += f.y;
        f = __half22float2(*(__half2*)&w0.x); b[0] += f.x; b[1] += f.y;
        f = __half22float2(*(__half2*)&w0.y); b[2] += f.x; b[3] += f.y;
        f = __half22float2(*(__half2*)&w1.x); b[4] += f.x; b[5] += f.y;
        f = __half22float2(*(__half2*)&w1.y); b[6] += f.x; b[7] += f.y;
        f = __half22float2(*(__half2*)&w2.x); b[8] += f.x; b[9] += f.y;
        f = __half22float2(*(__half2*)&w2.y); b[10] += f.x; b[11] += f.y;
    }
    if (e < end) {
        const uint2* p0 = (const uint2*)(hs + (size_t)csrc[e] * HID) + lane;
        uint2 u0 = p0[0], u1 = p0[32], u2 = p0[64];
        float2 f;
        f = __half22float2(*(__half2*)&u0.x); a[0] += f.x; a[1] += f.y;
        f = __half22float2(*(__half2*)&u0.y); a[2] += f.x; a[3] += f.y;
        f = __half22float2(*(__half2*)&u1.x); a[4] += f.x; a[5] += f.y;
        f = __half22float2(*(__half2*)&u1.y); a[6] += f.x; a[7] += f.y;
        f = __half22float2(*(__half2*)&u2.x); a[8] += f.x; a[9] += f.y;
        f = __half22float2(*(__half2*)&u2.y); a[10] += f.x; a[11] += f.y;
    }

    float iv = 1.0f / fmaxf((float)(end - beg), 1.0f);
    uint2* o = (uint2*)(agg + (size_t)node * HID) + lane;
    uint2 r;
    r.x = h2pack((a[0]+b[0])*iv, (a[1]+b[1])*iv);
    r.y = h2pack((a[2]+b[2])*iv, (a[3]+b[3])*iv);
    o[0] = r;
    r.x = h2pack((a[4]+b[4])*iv, (a[5]+b[5])*iv);
    r.y = h2pack((a[6]+b[6])*iv, (a[7]+b[7])*iv);
    o[32] = r;
    r.x = h2pack((a[8]+b[8])*iv, (a[9]+b[9])*iv);
    r.y = h2pack((a[10]+b[10])*iv, (a[11]+b[11])*iv);
    o[64] = r;
}

// width 10: thread per (node, feature), fp32 source
__global__ void k_gather10(const int* __restrict__ rowptr, const int* __restrict__ csrc,
                           const float* __restrict__ x, float* __restrict__ agg, int n) {
    int idx = blockIdx.x * blockDim.x + threadIdx.x;
    if (idx >= n * IN_DIM) return;
    int node = idx / IN_DIM, f = idx % IN_DIM;
    int beg = rowptr[node], end = rowptr[node + 1];
    float a = 0.0f;
    for (int e = beg; e < end; e++)
        a += x[(size_t)csrc[e] * IN_DIM + f];
    agg[idx] = a / fmaxf((float)(end - beg), 1.0f);
}

// ---------------------------------------------------------------------------
// Layer 0 SAGE: K=10, 32 rows/block, 384 threads; writes fp16 only
// ---------------------------------------------------------------------------
#define L0R 32
__global__ void k_layer0(const float* __restrict__ agg, const float* __restrict__ x,
                         const float* __restrict__ Wl, const float* __restrict__ bl,
                         const float* __restrict__ Wr,
                         const float* __restrict__ bng, const float* __restrict__ bnb,
                         const float* __restrict__ bnm, const float* __restrict__ bnv,
                         __half* __restrict__ hs, int n) {
    __shared__ float sA[L0R][IN_DIM];
    __shared__ float sX[L0R][IN_DIM];
    __shared__ float red[L0R];
    int t = threadIdx.x;
    int row0 = blockIdx.x * L0R;

    if (t < L0R * IN_DIM) {
        int r = t / IN_DIM, k = t % IN_DIM;
        int row = row0 + r;
        sA[r][k] = (row < n) ? agg[(size_t)row * IN_DIM + k] : 0.0f;
        sX[r][k] = (row < n) ? x[(size_t)row * IN_DIM + k] : 0.0f;
    } else if (t < L0R * IN_DIM + L0R) {
        red[t - L0R * IN_DIM] = 0.0f;
    }
    __syncthreads();

    int j = t;
    float wl[IN_DIM], wr[IN_DIM];
#pragma unroll
    for (int k = 0; k < IN_DIM; k++) {
        wl[k] = Wl[j * IN_DIM + k];
        wr[k] = Wr[j * IN_DIM + k];
    }
    float bb = bl[j];

    float v[L0R];
#pragma unroll
    for (int r = 0; r < L0R; r++) {
        float s = bb;
#pragma unroll
        for (int k = 0; k < IN_DIM; k++)
            s += sA[r][k] * wl[k] + sX[r][k] * wr[k];
        v[r] = s;
    }

    int lane = t & 31;
#pragma unroll
    for (int r = 0; r < L0R; r++) {
        float p = v[r] * v[r];
#pragma unroll
        for (int o = 16; o > 0; o >>= 1) p += __shfl_xor_sync(0xFFFFFFFFu, p, o);
        if (lane == 0) atomicAdd(&red[r], p);
    }
    __syncthreads();

    float gm = bng[j], gb = bnb[j], mm = bnm[j], vv = bnv[j];
    float bscale = rsqrtf(vv + BN_EPS) * gm;
#pragma unroll
    for (int r = 0; r < L0R; r++) {
        int row = row0 + r;
        if (row >= n) continue;
        float sc = 1.0f / fmaxf(sqrtf(red[r]), 1e-12f);
        float val = elu_f((v[r] * sc - mm) * bscale + gb);
        hs[(size_t)row * HID + j] = __float2half(val);
    }
}

// ---------------------------------------------------------------------------
// R11-proven dual fp16 GEMM (double-buffered stages, 1 bar/iter, ldmatrix)
//   C[64, 384] = A1*W1^T + A2*W2^T + bias ; L2-normalize row, BN, ELU -> fp16
// ---------------------------------------------------------------------------
#define HSTR 24
#define ABUF (64 * HSTR)
#define WBUF (384 * HSTR)
#define MMA_DSMEM ((2 * ABUF + 2 * WBUF) * 2)   // 43008 B

__global__ void __launch_bounds__(512, 1)
k_mma(const __half* __restrict__ A1, const __half* __restrict__ W1,
      const float* __restrict__ bias,
      const __half* __restrict__ A2, const __half* __restrict__ W2,
      const float* __restrict__ bng, const float* __restrict__ bnb,
      const float* __restrict__ bnm, const float* __restrict__ bnv,
      __half* __restrict__ outh, int nrows) {
    extern __shared__ __half smh[];
    __half* AsB0 = smh;
    __half* AsB1 = smh + ABUF;
    __half* WsB0 = smh + 2 * ABUF;
    __half* WsB1 = smh + 2 * ABUF + WBUF;

    __shared__ float sSB[HID], sS2[HID], sAD[HID];
    __shared__ float red[64];

    const int tid  = threadIdx.x;
    const int lane = tid & 31;
    const int wid  = tid >> 5;
    const int rw   = wid & 1;
    const int cw   = wid >> 1;
    const int g    = lane >> 2;
    const int t4   = lane & 3;
    const int warpRow = rw * 32;
    const int cb   = cw * 48;
    const int rb   = blockIdx.x * 64;

    for (int c = tid; c < HID; c += 512) {
        float s2 = rsqrtf(bnv[c] + BN_EPS) * bng[c];
        sSB[c] = bias[c];
        sS2[c] = s2;
        sAD[c] = bnb[c] - bnm[c] * s2;
    }
    if (tid < 64) red[tid] = 0.0f;

    const int m8 = lane >> 3;
    const int r8 = lane & 7;
    uint32_t aAddr[2][2], bAddr[2][3];
    {
        int rowi = (m8 & 1) * 8 + r8;
        int koff = (m8 >> 1) * 8;
        int nrowi = (m8 >> 1) * 8 + r8;
        int nkoff = (m8 & 1) * 8;
#pragma unroll
        for (int mt = 0; mt < 2; mt++) {
            int off = (warpRow + mt * 16 + rowi) * HSTR + koff;
            aAddr[0][mt] = smem_u32(&AsB0[off]);
            aAddr[1][mt] = smem_u32(&AsB1[off]);
        }
#pragma unroll
        for (int p = 0; p < 3; p++) {
            int off = (cb + p * 16 + nrowi) * HSTR + nkoff;
            bAddr[0][p] = smem_u32(&WsB0[off]);
            bAddr[1][p] = smem_u32(&WsB1[off]);
        }
    }

    const int ar = tid >> 2, aq = tid & 3;
    const int aOff = ar * HSTR + aq * 4;
    int wr_[3], wq_[3], wOff[3];
#pragma unroll
    for (int i = 0; i < 3; i++) {
        int idx = tid + i * 512;
        wr_[i] = idx >> 2;
        wq_[i] = idx & 3;
        wOff[i] = wr_[i] * HSTR + wq_[i] * 4;
    }

    const int S = 48;

    float acc[2][6][4];
#pragma unroll
    for (int mt = 0; mt < 2; mt++)
#pragma unroll
        for (int nt = 0; nt < 6; nt++)
#pragma unroll
            for (int q = 0; q < 4; q++) acc[mt][nt][q] = 0.0f;

    uint2 avP = make_uint2(0u, 0u);
    uint2 wvP[3];

    {
        if (tid < 256) {
            int row = rb + ar;
            if (row < nrows)
                avP = *(const uint2*)(A1 + (size_t)row * HID + aq * 4);
        }
#pragma unroll
        for (int i = 0; i < 3; i++)
            wvP[i] = *(const uint2*)(W1 + (size_t)wr_[i] * HID + wq_[i] * 4);
        if (tid < 256)
            *(uint2*)&AsB0[aOff] = avP;
#pragma unroll
        for (int i = 0; i < 3; i++)
            *(uint2*)&WsB0[wOff[i]] = wvP[i];
    }

    for (int it = 0; it < S; it++) {
        const int b = it & 1;
        __syncthreads();

        if (it + 1 < S) {
            const int itn = it + 1;
            const int pass = itn / 24;
            const int k0 = (itn - pass * 24) * 16;
            const __half* A = pass ? A2 : A1;
            const __half* W = pass ? W2 : W1;
            if (tid < 256) {
                int row = rb + ar;
                avP = make_uint2(0u, 0u);
                if (row < nrows)
                    avP = *(const uint2*)(A + (size_t)row * HID + k0 + aq * 4);
            }
#pragma unroll
            for (int i = 0; i < 3; i++)
                wvP[i] = *(const uint2*)(W + (size_t)wr_[i] * HID + k0 + wq_[i] * 4);
        }

        {
            uint32_t a[2][4];
            LDSM_X4(a[0][0], a[0][1], a[0][2], a[0][3], aAddr[b][0]);
            LDSM_X4(a[1][0], a[1][1], a[1][2], a[1][3], aAddr[b][1]);
            uint32_t bfr[12];
            LDSM_X4(bfr[0], bfr[1], bfr[2],  bfr[3],  bAddr[b][0]);
            LDSM_X4(bfr[4], bfr[5], bfr[6],  bfr[7],  bAddr[b][1]);
            LDSM_X4(bfr[8], bfr[9], bfr[10], bfr[11], bAddr[b][2]);
#pragma unroll
            for (int nt = 0; nt < 6; nt++) {
                uint32_t b0 = bfr[nt * 2], b1 = bfr[nt * 2 + 1];
                mma_f16(acc[0][nt], a[0][0], a[0][1], a[0][2], a[0][3], b0, b1);
                mma_f16(acc[1][nt], a[1][0], a[1][1], a[1][2], a[1][3], b0, b1);
            }
        }

        if (it + 1 < S) {
            __half* An = b ? AsB0 : AsB1;
            __half* Wn = b ? WsB0 : WsB1;
            if (tid < 256)
                *(uint2*)&An[aOff] = avP;
#pragma unroll
            for (int i = 0; i < 3; i++)
                *(uint2*)&Wn[wOff[i]] = wvP[i];
        }
    }
    __syncthreads();

    // epilogue: bias, L2 norm, BN, ELU
#pragma unroll
    for (int nt = 0; nt < 6; nt++) {
        int col = cb + nt * 8 + 2 * t4;
        float b0 = sSB[col], b1 = sSB[col + 1];
#pragma unroll
        for (int mt = 0; mt < 2; mt++) {
            acc[mt][nt][0] += b0; acc[mt][nt][1] += b1;
            acc[mt][nt][2] += b0; acc[mt][nt][3] += b1;
        }
    }
#pragma unroll
    for (int mt = 0; mt < 2; mt++) {
        float s0 = 0.0f, s1 = 0.0f;
#pragma unroll
        for (int nt = 0; nt < 6; nt++) {
            s0 = fmaf(acc[mt][nt][0], acc[mt][nt][0], s0);
            s0 = fmaf(acc[mt][nt][1], acc[mt][nt][1], s0);
            s1 = fmaf(acc[mt][nt][2], acc[mt][nt][2], s1);
            s1 = fmaf(acc[mt][nt][3], acc[mt][nt][3], s1);
        }
        s0 += __shfl_xor_sync(0xFFFFFFFFu, s0, 1);
        s0 += __shfl_xor_sync(0xFFFFFFFFu, s0, 2);
        s1 += __shfl_xor_sync(0xFFFFFFFFu, s1, 1);
        s1 += __shfl_xor_sync(0xFFFFFFFFu, s1, 2);
        if (t4 == 0) {
            atomicAdd(&red[warpRow + mt * 16 + g], s0);
            atomicAdd(&red[warpRow + mt * 16 + g + 8], s1);
        }
    }
    __syncthreads();
    float sc0[2], sc1[2];
#pragma unroll
    for (int mt = 0; mt < 2; mt++) {
        sc0[mt] = 1.0f / fmaxf(sqrtf(red[warpRow + mt * 16 + g]), 1e-12f);
        sc1[mt] = 1.0f / fmaxf(sqrtf(red[warpRow + mt * 16 + g + 8]), 1e-12f);
    }

#pragma unroll
    for (int mt = 0; mt < 2; mt++) {
        int row0 = rb + warpRow + mt * 16 + g;
        int row1 = row0 + 8;
        bool v0r = (row0 < nrows), v1r = (row1 < nrows);
#pragma unroll
        for (int nt = 0; nt < 6; nt++) {
            int col = cb + nt * 8 + 2 * t4;
            float m0 = sS2[col], m1 = sS2[col + 1];
            float d0 = sAD[col], d1 = sAD[col + 1];
            float x0 = elu_f(acc[mt][nt][0] * sc0[mt] * m0 + d0);
            float x1 = elu_f(acc[mt][nt][1] * sc0[mt] * m1 + d1);
            float x2 = elu_f(acc[mt][nt][2] * sc1[mt] * m0 + d0);
            float x3 = elu_f(acc[mt][nt][3] * sc1[mt] * m1 + d1);
            if (v0r) *(uint32_t*)(outh + (size_t)row0 * HID + col) = h2pack(x0, x1);
            if (v1r) *(uint32_t*)(outh + (size_t)row1 * HID + col) = h2pack(x2, x3);
        }
    }
}

// ---------------------------------------------------------------------------
// Fused projection MLP: h1 = relu(bn0(A@Wp0^T+bp0)) kept in SMEM;
// h2 = relu(bn1(h1@Wp1^T+bp1)); out = h2@Wp2^T + bp2.
// Persistent A tile (stride 392 halves), W double-buffered.
// ---------------------------------------------------------------------------
#define ASTR2 392
#define AT_HALVES (64 * ASTR2)                 // 25088
#define PROJ_DSMEM ((AT_HALVES + 2 * WBUF) * 2) // 87040 B

__global__ void __launch_bounds__(512, 1)
k_proj(const __half* __restrict__ A1,
       const __half* __restrict__ W1, const float* __restrict__ b0v,
       const __half* __restrict__ W2, const float* __restrict__ b1v,
       const float* __restrict__ pg, const float* __restrict__ pb,
       const float* __restrict__ pm, const float* __restrict__ pv,
       const float* __restrict__ Wp2, const float* __restrict__ bp2,
       float* __restrict__ outf, int nrows) {
    extern __shared__ __half smh[];
    __half* At   = smh;
    __half* WsB0 = smh + AT_HALVES;
    __half* WsB1 = smh + AT_HALVES + WBUF;

    __shared__ float sSB0[HID], sS20[HID], sAD0[HID];
    __shared__ float sSB1[HID], sS21[HID], sAD1[HID];
    __shared__ float sWp[3 * HID];
    __shared__ float redF[192];

    const int tid  = threadIdx.x;
    const int lane = tid & 31;
    const int wid  = tid >> 5;
    const int rw   = wid & 1;
    const int cw   = wid >> 1;
    const int g    = lane >> 2;
    const int t4   = lane & 3;
    const int warpRow = rw * 32;
    const int cb   = cw * 48;
    const int rb   = blockIdx.x * 64;

    for (int c = tid; c < HID; c += 512) {
        float s2 = rsqrtf(pv[c] + BN_EPS) * pg[c];
        sSB0[c] = b0v[c];
        sS20[c] = s2;
        sAD0[c] = pb[c] - pm[c] * s2;
        float s2b = rsqrtf(pv[HID + c] + BN_EPS) * pg[HID + c];
        sSB1[c] = b1v[c];
        sS21[c] = s2b;
        sAD1[c] = pb[HID + c] - pm[HID + c] * s2b;
    }
    if (tid < 192) redF[tid] = 0.0f;
    for (int c = tid; c < 3 * HID; c += 512) sWp[c] = Wp2[c];

    // load A tile (64 rows x 96 uint2)
#pragma unroll
    for (int j = 0; j < 12; j++) {
        int idx = tid + j * 512;
        int r = idx / 96, c = idx % 96;
        uint2 v = make_uint2(0u, 0u);
        if (rb + r < nrows)
            v = *(const uint2*)(A1 + (size_t)(rb + r) * HID + c * 4);
        *(uint2*)&At[r * ASTR2 + c * 4] = v;
    }

    // ldmatrix addresses
    const int m8 = lane >> 3;
    const int r8 = lane & 7;
    uint32_t aBase[2], bAddr[2][3];
    {
        int rowi = (m8 & 1) * 8 + r8;
        int koffq = (m8 >> 1) * 8;
        int nrowi = (m8 >> 1) * 8 + r8;
        int nkoff = (m8 & 1) * 8;
#pragma unroll
        for (int mt = 0; mt < 2; mt++)
            aBase[mt] = smem_u32(&At[(warpRow + mt * 16 + rowi) * ASTR2 + koffq]);
#pragma unroll
        for (int p = 0; p < 3; p++) {
            int off = (cb + p * 16 + nrowi) * HSTR + nkoff;
            bAddr[0][p] = smem_u32(&WsB0[off]);
            bAddr[1][p] = smem_u32(&WsB1[off]);
        }
    }

    int wr_[3], wq_[3], wOff[3];
#pragma unroll
    for (int i = 0; i < 3; i++) {
        int idx = tid + i * 512;
        wr_[i] = idx >> 2;
        wq_[i] = idx & 3;
        wOff[i] = wr_[i] * HSTR + wq_[i] * 4;
    }

    float acc[2][6][4];
    uint2 wvP[3];

    for (int stage = 0; stage < 2; stage++) {
        const __half* W = stage ? W2 : W1;
#pragma unroll
        for (int mt = 0; mt < 2; mt++)
#pragma unroll
            for (int nt = 0; nt < 6; nt++)
#pragma unroll
                for (int q = 0; q < 4; q++) acc[mt][nt][q] = 0.0f;

        // stage W chunk 0 -> buf 0
#pragma unroll
        for (int i = 0; i < 3; i++) {
            wvP[i] = *(const uint2*)(W + (size_t)wr_[i] * HID + wq_[i] * 4);
            *(uint2*)&WsB0[wOff[i]] = wvP[i];
        }

        for (int it = 0; it < 24; it++) {
            const int b = it & 1;
            __syncthreads();

            if (it + 1 < 24) {
                const int k0 = (it + 1) * 16;
#pragma unroll
                for (int i = 0; i < 3; i++)
                    wvP[i] = *(const uint2*)(W + (size_t)wr_[i] * HID + k0 + wq_[i] * 4);
            }

            {
                const uint32_t ko = (uint32_t)(it * 32);
                uint32_t a[2][4];
                LDSM_X4(a[0][0], a[0][1], a[0][2], a[0][3], aBase[0] + ko);
                LDSM_X4(a[1][0], a[1][1], a[1][2], a[1][3], aBase[1] + ko);
                uint32_t bfr[12];
                LDSM_X4(bfr[0], bfr[1], bfr[2],  bfr[3],  bAddr[b][0]);
                LDSM_X4(bfr[4], bfr[5], bfr[6],  bfr[7],  bAddr[b][1]);
                LDSM_X4(bfr[8], bfr[9], bfr[10], bfr[11], bAddr[b][2]);
#pragma unroll
                for (int nt = 0; nt < 6; nt++) {
                    uint32_t b0 = bfr[nt * 2], b1 = bfr[nt * 2 + 1];
                    mma_f16(acc[0][nt], a[0][0], a[0][1], a[0][2], a[0][3], b0, b1);
                    mma_f16(acc[1][nt], a[1][0], a[1][1], a[1][2], a[1][3], b0, b1);
                }
            }

            if (it + 1 < 24) {
                __half* Wn = b ? WsB0 : WsB1;
#pragma unroll
                for (int i = 0; i < 3; i++)
                    *(uint2*)&Wn[wOff[i]] = wvP[i];
            }
        }
        __syncthreads();

        if (stage == 0) {
            // epilogue 1: bias, BN0, ReLU -> write back into At
#pragma unroll
            for (int mt = 0; mt < 2; mt++) {
                int lr0 = warpRow + mt * 16 + g;
                int lr1 = lr0 + 8;
#pragma unroll
                for (int nt = 0; nt < 6; nt++) {
                    int col = cb + nt * 8 + 2 * t4;
                    float bb0 = sSB0[col], bb1 = sSB0[col + 1];
                    float m0 = sS20[col], m1 = sS20[col + 1];
                    float d0 = sAD0[col], d1 = sAD0[col + 1];
                    float x0 = fmaxf((acc[mt][nt][0] + bb0) * m0 + d0, 0.0f);
                    float x1 = fmaxf((acc[mt][nt][1] + bb1) * m1 + d1, 0.0f);
                    float x2 = fmaxf((acc[mt][nt][2] + bb0) * m0 + d0, 0.0f);
                    float x3 = fmaxf((acc[mt][nt][3] + bb1) * m1 + d1, 0.0f);
                    *(uint32_t*)&At[lr0 * ASTR2 + col] = h2pack(x0, x1);
                    *(uint32_t*)&At[lr1 * ASTR2 + col] = h2pack(x2, x3);
                }
            }
            // next stage's top-of-loop barrier orders these writes
        }
    }

    // epilogue 2: bias, BN1, ReLU, project to 3 outputs
    {
        float p0[2][3], p1[2][3];
#pragma unroll
        for (int mt = 0; mt < 2; mt++)
#pragma unroll
            for (int o = 0; o < 3; o++) { p0[mt][o] = 0.0f; p1[mt][o] = 0.0f; }

#pragma unroll
        for (int mt = 0; mt < 2; mt++) {
#pragma unroll
            for (int nt = 0; nt < 6; nt++) {
                int col = cb + nt * 8 + 2 * t4;
                float bb0 = sSB1[col], bb1 = sSB1[col + 1];
                float m0 = sS21[col], m1 = sS21[col + 1];
                float d0 = sAD1[col], d1 = sAD1[col + 1];
                float x0 = fmaxf((acc[mt][nt][0] + bb0) * m0 + d0, 0.0f);
                float x1 = fmaxf((acc[mt][nt][1] + bb1) * m1 + d1, 0.0f);
                float x2 = fmaxf((acc[mt][nt][2] + bb0) * m0 + d0, 0.0f);
                float x3 = fmaxf((acc[mt][nt][3] + bb1) * m1 + d1, 0.0f);
#pragma unroll
                for (int o = 0; o < 3; o++) {
                    float w0 = sWp[o * HID + col], w1 = sWp[o * HID + col + 1];
                    p0[mt][o] = fmaf(x0, w0, fmaf(x1, w1, p0[mt][o]));
                    p1[mt][o] = fmaf(x2, w0, fmaf(x3, w1, p1[mt][o]));
                }
            }
        }
#pragma unroll
        for (int mt = 0; mt < 2; mt++)
#pragma unroll
            for (int o = 0; o < 3; o++) {
                float v0 = p0[mt][o], v1 = p1[mt][o];
                v0 += __shfl_xor_sync(0xFFFFFFFFu, v0, 1);
                v0 += __shfl_xor_sync(0xFFFFFFFFu, v0, 2);
                v1 += __shfl_xor_sync(0xFFFFFFFFu, v1, 1);
                v1 += __shfl_xor_sync(0xFFFFFFFFu, v1, 2);
                if (t4 == 0) {
                    atomicAdd(&redF[(warpRow + mt * 16 + g) * 3 + o], v0);
                    atomicAdd(&redF[(warpRow + mt * 16 + g + 8) * 3 + o], v1);
                }
            }
        __syncthreads();
        if (tid < 64) {
            int row = rb + tid;
            if (row < nrows) {
                outf[(size_t)row * 3 + 0] = redF[tid * 3 + 0] + bp2[0];
                outf[(size_t)row * 3 + 1] = redF[tid * 3 + 1] + bp2[1];
                outf[(size_t)row * 3 + 2] = redF[tid * 3 + 2] + bp2[2];
            }
        }
    }
}

// ---------------------------------------------------------------------------
extern "C" void kernel_launch(void* const* d_in, const int* in_sizes, int n_in,
                              void* d_out, int out_size) {
    const float* x    = (const float*)d_in[0];
    const int*   ei   = (const int*)  d_in[1];
    const float* Wl0  = (const float*)d_in[2];
    const float* bl0  = (const float*)d_in[3];
    const float* Wr0  = (const float*)d_in[4];
    const float* Wl   = (const float*)d_in[5];
    const float* bl   = (const float*)d_in[6];
    const float* Wr   = (const float*)d_in[7];
    const float* bng  = (const float*)d_in[8];
    const float* bnb  = (const float*)d_in[9];
    const float* bnm  = (const float*)d_in[10];
    const float* bnv  = (const float*)d_in[11];
    const float* Wp0  = (const float*)d_in[12];
    const float* bp0  = (const float*)d_in[13];
    const float* Wp1  = (const float*)d_in[14];
    const float* bp1  = (const float*)d_in[15];
    const float* Wp2  = (const float*)d_in[16];
    const float* bp2  = (const float*)d_in[17];
    const float* pg   = (const float*)d_in[18];
    const float* pb   = (const float*)d_in[19];
    const float* pm   = (const float*)d_in[20];
    const float* pv   = (const float*)d_in[21];

    const int* src = ei;
    const int* dst = ei + EE;

    __half *agg16, *shA, *shB, *wl16, *wr16, *wp016, *wp116;
    float *agg10;
    int *deg, *inc, *rowptr, *cur, *csrc, *bsum;
    cudaGetSymbolAddress((void**)&agg16,  g_agg16);
    cudaGetSymbolAddress((void**)&shA,    g_shA);
    cudaGetSymbolAddress((void**)&shB,    g_shB);
    cudaGetSymbolAddress((void**)&agg10,  g_agg10);
    cudaGetSymbolAddress((void**)&wl16,   g_wl16);
    cudaGetSymbolAddress((void**)&wr16,   g_wr16);
    cudaGetSymbolAddress((void**)&wp016,  g_wp016);
    cudaGetSymbolAddress((void**)&wp116,  g_wp116);
    cudaGetSymbolAddress((void**)&deg,    g_deg);
    cudaGetSymbolAddress((void**)&inc,    g_inc);
    cudaGetSymbolAddress((void**)&rowptr, g_rowptr);
    cudaGetSymbolAddress((void**)&cur,    g_cur);
    cudaGetSymbolAddress((void**)&csrc,   g_csrc);
    cudaGetSymbolAddress((void**)&bsum,   g_bsum);

    cudaFuncSetAttribute(k_mma,  cudaFuncAttributeMaxDynamicSharedMemorySize, MMA_DSMEM);
    cudaFuncSetAttribute(k_proj, cudaFuncAttributeMaxDynamicSharedMemorySize, PROJ_DSMEM);

    // ---- weight conversion (single launch) ----
    {
        int ntot = (4 * WMAT + 4 * WMAT + WMAT + WMAT) / 4;
        k_cvt_all<<<(ntot + 255) / 256, 256>>>(
            (const float4*)Wl, (const float4*)Wr, (const float4*)Wp0, (const float4*)Wp1,
            (uint2*)wl16, (uint2*)wr16, (uint2*)wp016, (uint2*)wp116);
    }

    // ---- CSR build ----
    cudaMemsetAsync(deg, 0, NN * sizeof(int));
    k_hist<<<(EE + 255) / 256, 256>>>(dst, deg, EE);
    k_scan_block<<<NSCANB, SCAN_B>>>(deg, inc, bsum, NN);
    k_scan_bsum<<<1, 128>>>(bsum, NSCANB);
    k_csr_fin<<<(NN + 255) / 256, 256>>>(deg, inc, bsum, rowptr, cur, NN);
    k_fill<<<(EE + 255) / 256, 256>>>(src, dst, cur, csrc, EE);

    // ---- layer 0 (K=10) ----
    k_gather10<<<(NN * IN_DIM + 255) / 256, 256>>>(rowptr, csrc, x, agg10, NN);
    k_layer0<<<(NN + L0R - 1) / L0R, 384>>>(agg10, x, Wl0, bl0, Wr0,
                                            bng, bnb, bnm, bnv, shA, NN);

    // ---- layers 1..4: fp16 gather + dual fp16 mma GEMM (R11 path) ----
    const int gblocks = (NN + 63) / 64;
    for (int t = 1; t < TT; t++) {
        k_gather384<<<(NN * 32 + 255) / 256, 256>>>(rowptr, csrc, shA, agg16, NN);
        k_mma<<<gblocks, 512, MMA_DSMEM>>>(
            agg16, wl16 + (size_t)(t - 1) * WMAT, bl + (t - 1) * HID,
            shA,   wr16 + (size_t)(t - 1) * WMAT,
            bng + t * HID, bnb + t * HID, bnm + t * HID, bnv + t * HID,
            shB, NN);
        __half* ts = shA; shA = shB; shB = ts;
    }

    // ---- fused projection MLP (both GEMMs + final [384->3]) ----
    k_proj<<<gblocks, 512, PROJ_DSMEM>>>(shA, wp016, bp0, wp116, bp1,
                                         pg, pb, pm, pv, Wp2, bp2,
                                         (float*)d_out, NN);

    (void)in_sizes; (void)n_in; (void)out_size;
}

// round 14
// speedup vs baseline: 1.1991x; 1.1134x over previous
#include <cuda_runtime.h>
#include <cuda_fp16.h>
#include <math.h>
#include <cstdint>

#define NN 100000
#define EE 300000
#define IN_DIM 10
#define HID 384
#define TT 5
#define BN_EPS 1e-5f
#define WMAT (HID * HID)

#define SCAN_B 1024
#define NSCANB ((NN + SCAN_B - 1) / SCAN_B)   // 98

// Static scratch (allocation-free rule) — all activations fp16
__device__ __half  g_agg16[(size_t)NN * HID];
__device__ __half  g_shA [(size_t)NN * HID];
__device__ __half  g_shB [(size_t)NN * HID];
__device__ __half  g_wl16[4 * WMAT];
__device__ __half  g_wr16[4 * WMAT];
__device__ __half  g_wp016[WMAT];
__device__ __half  g_wp116[WMAT];
__device__ int   g_deg [NN];
__device__ int   g_inc [NN];
__device__ int   g_rowptr[NN + 1];
__device__ int   g_cur [NN];
__device__ int   g_csrc[EE];
__device__ int   g_bsum[128];

// ---------------------------------------------------------------------------
// helpers
// ---------------------------------------------------------------------------
__device__ __forceinline__ uint32_t smem_u32(const void* p) {
    uint32_t a;
    asm("{ .reg .u64 t; cvta.to.shared.u64 t, %1; cvt.u32.u64 %0, t; }" : "=r"(a) : "l"(p));
    return a;
}

__device__ __forceinline__ void mma_f16(float* c, uint32_t a0, uint32_t a1,
                                        uint32_t a2, uint32_t a3,
                                        uint32_t b0, uint32_t b1) {
    asm volatile("mma.sync.aligned.m16n8k16.row.col.f32.f16.f16.f32 "
                 "{%0,%1,%2,%3}, {%4,%5,%6,%7}, {%8,%9}, {%0,%1,%2,%3};"
                 : "+f"(c[0]), "+f"(c[1]), "+f"(c[2]), "+f"(c[3])
                 : "r"(a0), "r"(a1), "r"(a2), "r"(a3), "r"(b0), "r"(b1));
}

#define LDSM_X4(r0, r1, r2, r3, addr) \
    asm volatile("ldmatrix.sync.aligned.m8n8.x4.shared.b16 {%0,%1,%2,%3}, [%4];" \
                 : "=r"(r0), "=r"(r1), "=r"(r2), "=r"(r3) : "r"(addr))

__device__ __forceinline__ float elu_f(float v) {
    return (v > 0.0f) ? v : (__expf(v) - 1.0f);
}

__device__ __forceinline__ uint32_t h2pack(float x, float y) {
    __half2 h = __float22half2_rn(make_float2(x, y));
    return *(uint32_t*)&h;
}

// single fp32->fp16 conversion kernel covering all weight arrays
__global__ void k_cvt_all(const float4* __restrict__ wl, const float4* __restrict__ wr,
                          const float4* __restrict__ wp0, const float4* __restrict__ wp1,
                          uint2* __restrict__ owl, uint2* __restrict__ owr,
                          uint2* __restrict__ owp0, uint2* __restrict__ owp1) {
    const int n1 = 4 * WMAT / 4;
    const int n2 = n1 + 4 * WMAT / 4;
    const int n3 = n2 + WMAT / 4;
    const int n4 = n3 + WMAT / 4;
    int i = blockIdx.x * blockDim.x + threadIdx.x;
    if (i >= n4) return;
    const float4* s;
    uint2* d;
    int j;
    if (i < n1)      { s = wl;  d = owl;  j = i; }
    else if (i < n2) { s = wr;  d = owr;  j = i - n1; }
    else if (i < n3) { s = wp0; d = owp0; j = i - n2; }
    else             { s = wp1; d = owp1; j = i - n3; }
    float4 v = s[j];
    uint2 o;
    o.x = h2pack(v.x, v.y);
    o.y = h2pack(v.z, v.w);
    d[j] = o;
}

// ---------------------------------------------------------------------------
// CSR build
// ---------------------------------------------------------------------------
__global__ void k_hist(const int* __restrict__ dst, int* __restrict__ deg, int e) {
    int i = blockIdx.x * blockDim.x + threadIdx.x;
    if (i < e) atomicAdd(&deg[dst[i]], 1);
}

__global__ void k_scan_block(const int* __restrict__ deg, int* __restrict__ inc,
                             int* __restrict__ bsum, int n) {
    __shared__ int s[SCAN_B];
    int i = blockIdx.x * SCAN_B + threadIdx.x;
    s[threadIdx.x] = (i < n) ? deg[i] : 0;
    __syncthreads();
#pragma unroll
    for (int o = 1; o < SCAN_B; o <<= 1) {
        int t = (threadIdx.x >= o) ? s[threadIdx.x - o] : 0;
        __syncthreads();
        s[threadIdx.x] += t;
        __syncthreads();
    }
    if (i < n) inc[i] = s[threadIdx.x];
    if (threadIdx.x == SCAN_B - 1) bsum[blockIdx.x] = s[SCAN_B - 1];
}

__global__ void k_scan_bsum(int* __restrict__ bsum, int nb) {
    __shared__ int s[128];
    if (threadIdx.x < nb) s[threadIdx.x] = bsum[threadIdx.x];
    __syncthreads();
    if (threadIdx.x == 0) {
        int run = 0;
        for (int i = 0; i < nb; i++) { run += s[i]; s[i] = run; }
    }
    __syncthreads();
    if (threadIdx.x < nb) bsum[threadIdx.x] = s[threadIdx.x];
}

__global__ void k_csr_fin(const int* __restrict__ deg, const int* __restrict__ inc,
                          const int* __restrict__ bsum,
                          int* __restrict__ rowptr, int* __restrict__ cur, int n) {
    int i = blockIdx.x * blockDim.x + threadIdx.x;
    if (i >= n) return;
    int b = i / SCAN_B;
    int total = inc[i] + (b > 0 ? bsum[b - 1] : 0);
    rowptr[i + 1] = total;
    cur[i] = total - deg[i];
    if (i == 0) rowptr[0] = 0;
}

__global__ void k_fill(const int* __restrict__ src, const int* __restrict__ dst,
                       int* __restrict__ cur, int* __restrict__ csrc, int e) {
    int i = blockIdx.x * blockDim.x + threadIdx.x;
    if (i >= e) return;
    int pos = atomicAdd(&cur[dst[i]], 1);
    csrc[pos] = src[i];
}

// ---------------------------------------------------------------------------
// CSR mean-gather, width 384, fp16 in/out, fp32 accumulate, 2x unroll
// ---------------------------------------------------------------------------
__global__ void k_gather384(const int* __restrict__ rowptr, const int* __restrict__ csrc,
                            const __half* __restrict__ hs, __half* __restrict__ agg,
                            int n) {
    int node = (blockIdx.x * blockDim.x + threadIdx.x) >> 5;
    int lane = threadIdx.x & 31;
    if (node >= n) return;
    int beg = rowptr[node], end = rowptr[node + 1];
    float a[12], b[12];
#pragma unroll
    for (int i = 0; i < 12; i++) { a[i] = 0.0f; b[i] = 0.0f; }

    int e = beg;
    for (; e + 1 < end; e += 2) {
        int s0 = csrc[e], s1 = csrc[e + 1];
        const uint2* p0 = (const uint2*)(hs + (size_t)s0 * HID) + lane;
        const uint2* p1 = (const uint2*)(hs + (size_t)s1 * HID) + lane;
        uint2 u0 = p0[0], u1 = p0[32], u2 = p0[64];
        uint2 w0 = p1[0], w1 = p1[32], w2 = p1[64];
        float2 f;
        f = __half22float2(*(__half2*)&u0.x); a[0] += f.x; a[1] += f.y;
        f = __half22float2(*(__half2*)&u0.y); a[2] += f.x; a[3] += f.y;
        f = __half22float2(*(__half2*)&u1.x); a[4] += f.x; a[5] += f.y;
        f = __half22float2(*(__half2*)&u1.y); a[6] += f.x; a[7] += f.y;
        f = __half22float2(*(__half2*)&u2.x); a[8] += f.x; a[9] += f.y;
        f = __half22float2(*(__half2*)&u2.y); a[10] += f.x; a[11] += f.y;
        f = __half22float2(*(__half2*)&w0.x); b[0] += f.x; b[1] += f.y;
        f = __half22float2(*(__half2*)&w0.y); b[2] += f.x; b[3] += f.y;
        f = __half22float2(*(__half2*)&w1.x); b[4] += f.x; b[5] += f.y;
        f = __half22float2(*(__half2*)&w1.y); b[6] += f.x; b[7] += f.y;
        f = __half22float2(*(__half2*)&w2.x); b[8] += f.x; b[9] += f.y;
        f = __half22float2(*(__half2*)&w2.y); b[10] += f.x; b[11] += f.y;
    }
    if (e < end) {
        const uint2* p0 = (const uint2*)(hs + (size_t)csrc[e] * HID) + lane;
        uint2 u0 = p0[0], u1 = p0[32], u2 = p0[64];
        float2 f;
        f = __half22float2(*(__half2*)&u0.x); a[0] += f.x; a[1] += f.y;
        f = __half22float2(*(__half2*)&u0.y); a[2] += f.x; a[3] += f.y;
        f = __half22float2(*(__half2*)&u1.x); a[4] += f.x; a[5] += f.y;
        f = __half22float2(*(__half2*)&u1.y); a[6] += f.x; a[7] += f.y;
        f = __half22float2(*(__half2*)&u2.x); a[8] += f.x; a[9] += f.y;
        f = __half22float2(*(__half2*)&u2.y); a[10] += f.x; a[11] += f.y;
    }

    float iv = 1.0f / fmaxf((float)(end - beg), 1.0f);
    uint2* o = (uint2*)(agg + (size_t)node * HID) + lane;
    uint2 r;
    r.x = h2pack((a[0]+b[0])*iv, (a[1]+b[1])*iv);
    r.y = h2pack((a[2]+b[2])*iv, (a[3]+b[3])*iv);
    o[0] = r;
    r.x = h2pack((a[4]+b[4])*iv, (a[5]+b[5])*iv);
    r.y = h2pack((a[6]+b[6])*iv, (a[7]+b[7])*iv);
    o[32] = r;
    r.x = h2pack((a[8]+b[8])*iv, (a[9]+b[9])*iv);
    r.y = h2pack((a[10]+b[10])*iv, (a[11]+b[11])*iv);
    o[64] = r;
}

// ---------------------------------------------------------------------------
// Layer 0 SAGE: K=10, 32 rows/block, 384 threads; fused CSR mean-gather.
// ---------------------------------------------------------------------------
#define L0R 32
__global__ void k_layer0(const int* __restrict__ rowptr, const int* __restrict__ csrc,
                         const float* __restrict__ x,
                         const float* __restrict__ Wl, const float* __restrict__ bl,
                         const float* __restrict__ Wr,
                         const float* __restrict__ bng, const float* __restrict__ bnb,
                         const float* __restrict__ bnm, const float* __restrict__ bnv,
                         __half* __restrict__ hs, int n) {
    __shared__ float sA[L0R][IN_DIM];
    __shared__ float sX[L0R][IN_DIM];
    __shared__ float red[L0R];
    int t = threadIdx.x;
    int row0 = blockIdx.x * L0R;

    if (t < L0R * IN_DIM) {
        int r = t / IN_DIM, f = t % IN_DIM;
        int row = row0 + r;
        float a = 0.0f, xv = 0.0f;
        if (row < n) {
            xv = x[(size_t)row * IN_DIM + f];
            int beg = rowptr[row], end = rowptr[row + 1];
            for (int e = beg; e < end; e++)
                a += x[(size_t)csrc[e] * IN_DIM + f];
            a /= fmaxf((float)(end - beg), 1.0f);
        }
        sA[r][f] = a;
        sX[r][f] = xv;
    } else if (t < L0R * IN_DIM + L0R) {
        red[t - L0R * IN_DIM] = 0.0f;
    }
    __syncthreads();

    int j = t;
    float wl[IN_DIM], wr[IN_DIM];
#pragma unroll
    for (int k = 0; k < IN_DIM; k++) {
        wl[k] = Wl[j * IN_DIM + k];
        wr[k] = Wr[j * IN_DIM + k];
    }
    float bb = bl[j];

    float v[L0R];
#pragma unroll
    for (int r = 0; r < L0R; r++) {
        float s = bb;
#pragma unroll
        for (int k = 0; k < IN_DIM; k++)
            s += sA[r][k] * wl[k] + sX[r][k] * wr[k];
        v[r] = s;
    }

    int lane = t & 31;
#pragma unroll
    for (int r = 0; r < L0R; r++) {
        float p = v[r] * v[r];
#pragma unroll
        for (int o = 16; o > 0; o >>= 1) p += __shfl_xor_sync(0xFFFFFFFFu, p, o);
        if (lane == 0) atomicAdd(&red[r], p);
    }
    __syncthreads();

    float gm = bng[j], gb = bnb[j], mm = bnm[j], vv = bnv[j];
    float bscale = rsqrtf(vv + BN_EPS) * gm;
#pragma unroll
    for (int r = 0; r < L0R; r++) {
        int row = row0 + r;
        if (row >= n) continue;
        float sc = 1.0f / fmaxf(sqrtf(red[r]), 1e-12f);
        float val = elu_f((v[r] * sc - mm) * bscale + gb);
        hs[(size_t)row * HID + j] = __float2half(val);
    }
}

// ---------------------------------------------------------------------------
// Dual fp16 GEMM — BK=32 (2 k16 chunks per stage), double-buffered, 1 bar/iter
//   C[64, 384] = A1*W1^T + A2*W2^T + bias ; L2-normalize row, BN, ELU -> fp16
// Row stride 40 halves (80 B): ldmatrix conflict-free (80r mod 128 distinct).
// ---------------------------------------------------------------------------
#define KSTR 40
#define ABUF2 (64 * KSTR)                    // 2560 halves
#define WBUF2 (384 * KSTR)                   // 15360 halves
#define MMA_DSMEM ((2 * ABUF2 + 2 * WBUF2) * 2)   // 71680 B

__global__ void __launch_bounds__(512, 1)
k_mma(const __half* __restrict__ A1, const __half* __restrict__ W1,
      const float* __restrict__ bias,
      const __half* __restrict__ A2, const __half* __restrict__ W2,
      const float* __restrict__ bng, const float* __restrict__ bnb,
      const float* __restrict__ bnm, const float* __restrict__ bnv,
      __half* __restrict__ outh, int nrows) {
    extern __shared__ __half smh[];
    __half* AsB0 = smh;
    __half* AsB1 = smh + ABUF2;
    __half* WsB0 = smh + 2 * ABUF2;
    __half* WsB1 = smh + 2 * ABUF2 + WBUF2;

    __shared__ float sSB[HID], sS2[HID], sAD[HID];
    __shared__ float red[64];

    const int tid  = threadIdx.x;
    const int lane = tid & 31;
    const int wid  = tid >> 5;
    const int rw   = wid & 1;
    const int cw   = wid >> 1;
    const int g    = lane >> 2;
    const int t4   = lane & 3;
    const int warpRow = rw * 32;
    const int cb   = cw * 48;
    const int rb   = blockIdx.x * 64;

    for (int c = tid; c < HID; c += 512) {
        float s2 = rsqrtf(bnv[c] + BN_EPS) * bng[c];
        sSB[c] = bias[c];
        sS2[c] = s2;
        sAD[c] = bnb[c] - bnm[c] * s2;
    }
    if (tid < 64) red[tid] = 0.0f;

    const int m8 = lane >> 3;
    const int r8 = lane & 7;
    uint32_t aAddr[2][2], bAddr[2][3];
    {
        int rowi = (m8 & 1) * 8 + r8;
        int koff = (m8 >> 1) * 8;
        int nrowi = (m8 >> 1) * 8 + r8;
        int nkoff = (m8 & 1) * 8;
#pragma unroll
        for (int mt = 0; mt < 2; mt++) {
            int off = (warpRow + mt * 16 + rowi) * KSTR + koff;
            aAddr[0][mt] = smem_u32(&AsB0[off]);
            aAddr[1][mt] = smem_u32(&AsB1[off]);
        }
#pragma unroll
        for (int p = 0; p < 3; p++) {
            int off = (cb + p * 16 + nrowi) * KSTR + nkoff;
            bAddr[0][p] = smem_u32(&WsB0[off]);
            bAddr[1][p] = smem_u32(&WsB1[off]);
        }
    }

    // staging: A 64x32 halves (512 uint2, 1/thread); W 384x32 (3072 uint2, 6/thread)
    const int ar = tid >> 3, aq = tid & 7;
    const int aOff = ar * KSTR + aq * 4;
    int wr_[6], wq_[6], wOff[6];
#pragma unroll
    for (int i = 0; i < 6; i++) {
        int idx = tid + i * 512;
        wr_[i] = idx >> 3;
        wq_[i] = idx & 7;
        wOff[i] = wr_[i] * KSTR + wq_[i] * 4;
    }

    const int S = 24;   // 2 passes x 12 iters (32 k per iter)

    float acc[2][6][4];
#pragma unroll
    for (int mt = 0; mt < 2; mt++)
#pragma unroll
        for (int nt = 0; nt < 6; nt++)
#pragma unroll
            for (int q = 0; q < 4; q++) acc[mt][nt][q] = 0.0f;

    uint2 avP = make_uint2(0u, 0u);
    uint2 wvP[6];

    // prologue: chunk 0 -> buf 0
    {
        int row = rb + ar;
        if (row < nrows)
            avP = *(const uint2*)(A1 + (size_t)row * HID + aq * 4);
#pragma unroll
        for (int i = 0; i < 6; i++)
            wvP[i] = *(const uint2*)(W1 + (size_t)wr_[i] * HID + wq_[i] * 4);
        *(uint2*)&AsB0[aOff] = avP;
#pragma unroll
        for (int i = 0; i < 6; i++)
            *(uint2*)&WsB0[wOff[i]] = wvP[i];
    }

    for (int it = 0; it < S; it++) {
        const int b = it & 1;
        __syncthreads();

        // prefetch iter it+1
        if (it + 1 < S) {
            const int itn = it + 1;
            const int pass = itn / 12;
            const int k0 = (itn - pass * 12) * 32;
            const __half* A = pass ? A2 : A1;
            const __half* W = pass ? W2 : W1;
            int row = rb + ar;
            avP = make_uint2(0u, 0u);
            if (row < nrows)
                avP = *(const uint2*)(A + (size_t)row * HID + k0 + aq * 4);
#pragma unroll
            for (int i = 0; i < 6; i++)
                wvP[i] = *(const uint2*)(W + (size_t)wr_[i] * HID + k0 + wq_[i] * 4);
        }

        // compute: 2 chunks x (5 ldmatrix + 12 MMA)
#pragma unroll
        for (int c = 0; c < 2; c++) {
            const uint32_t ko = (uint32_t)(c * 32);   // 16 halves = 32 B
            uint32_t a[2][4];
            LDSM_X4(a[0][0], a[0][1], a[0][2], a[0][3], aAddr[b][0] + ko);
            LDSM_X4(a[1][0], a[1][1], a[1][2], a[1][3], aAddr[b][1] + ko);
            uint32_t bfr[12];
            LDSM_X4(bfr[0], bfr[1], bfr[2],  bfr[3],  bAddr[b][0] + ko);
            LDSM_X4(bfr[4], bfr[5], bfr[6],  bfr[7],  bAddr[b][1] + ko);
            LDSM_X4(bfr[8], bfr[9], bfr[10], bfr[11], bAddr[b][2] + ko);
#pragma unroll
            for (int nt = 0; nt < 6; nt++) {
                uint32_t b0 = bfr[nt * 2], b1 = bfr[nt * 2 + 1];
                mma_f16(acc[0][nt], a[0][0], a[0][1], a[0][2], a[0][3], b0, b1);
                mma_f16(acc[1][nt], a[1][0], a[1][1], a[1][2], a[1][3], b0, b1);
            }
        }

        // stage iter it+1 into the other buffer
        if (it + 1 < S) {
            __half* An = b ? AsB0 : AsB1;
            __half* Wn = b ? WsB0 : WsB1;
            *(uint2*)&An[aOff] = avP;
#pragma unroll
            for (int i = 0; i < 6; i++)
                *(uint2*)&Wn[wOff[i]] = wvP[i];
        }
    }
    __syncthreads();

    // epilogue: bias, L2 norm, BN, ELU
#pragma unroll
    for (int nt = 0; nt < 6; nt++) {
        int col = cb + nt * 8 + 2 * t4;
        float b0 = sSB[col], b1 = sSB[col + 1];
#pragma unroll
        for (int mt = 0; mt < 2; mt++) {
            acc[mt][nt][0] += b0; acc[mt][nt][1] += b1;
            acc[mt][nt][2] += b0; acc[mt][nt][3] += b1;
        }
    }
#pragma unroll
    for (int mt = 0; mt < 2; mt++) {
        float s0 = 0.0f, s1 = 0.0f;
#pragma unroll
        for (int nt = 0; nt < 6; nt++) {
            s0 = fmaf(acc[mt][nt][0], acc[mt][nt][0], s0);
            s0 = fmaf(acc[mt][nt][1], acc[mt][nt][1], s0);
            s1 = fmaf(acc[mt][nt][2], acc[mt][nt][2], s1);
            s1 = fmaf(acc[mt][nt][3], acc[mt][nt][3], s1);
        }
        s0 += __shfl_xor_sync(0xFFFFFFFFu, s0, 1);
        s0 += __shfl_xor_sync(0xFFFFFFFFu, s0, 2);
        s1 += __shfl_xor_sync(0xFFFFFFFFu, s1, 1);
        s1 += __shfl_xor_sync(0xFFFFFFFFu, s1, 2);
        if (t4 == 0) {
            atomicAdd(&red[warpRow + mt * 16 + g], s0);
            atomicAdd(&red[warpRow + mt * 16 + g + 8], s1);
        }
    }
    __syncthreads();
    float sc0[2], sc1[2];
#pragma unroll
    for (int mt = 0; mt < 2; mt++) {
        sc0[mt] = 1.0f / fmaxf(sqrtf(red[warpRow + mt * 16 + g]), 1e-12f);
        sc1[mt] = 1.0f / fmaxf(sqrtf(red[warpRow + mt * 16 + g + 8]), 1e-12f);
    }

#pragma unroll
    for (int mt = 0; mt < 2; mt++) {
        int row0 = rb + warpRow + mt * 16 + g;
        int row1 = row0 + 8;
        bool v0r = (row0 < nrows), v1r = (row1 < nrows);
#pragma unroll
        for (int nt = 0; nt < 6; nt++) {
            int col = cb + nt * 8 + 2 * t4;
            float m0 = sS2[col], m1 = sS2[col + 1];
            float d0 = sAD[col], d1 = sAD[col + 1];
            float x0 = elu_f(acc[mt][nt][0] * sc0[mt] * m0 + d0);
            float x1 = elu_f(acc[mt][nt][1] * sc0[mt] * m1 + d1);
            float x2 = elu_f(acc[mt][nt][2] * sc1[mt] * m0 + d0);
            float x3 = elu_f(acc[mt][nt][3] * sc1[mt] * m1 + d1);
            if (v0r) *(uint32_t*)(outh + (size_t)row0 * HID + col) = h2pack(x0, x1);
            if (v1r) *(uint32_t*)(outh + (size_t)row1 * HID + col) = h2pack(x2, x3);
        }
    }
}

// ---------------------------------------------------------------------------
// Fused projection MLP (R13-proven): h1 = relu(bn0(A@Wp0^T+bp0)) in SMEM;
// h2 = relu(bn1(h1@Wp1^T+bp1)); out = h2@Wp2^T + bp2.
// ---------------------------------------------------------------------------
#define HSTR 24
#define WBUF (384 * HSTR)
#define ASTR2 392
#define AT_HALVES (64 * ASTR2)
#define PROJ_DSMEM ((AT_HALVES + 2 * WBUF) * 2)

__global__ void __launch_bounds__(512, 1)
k_proj(const __half* __restrict__ A1,
       const __half* __restrict__ W1, const float* __restrict__ b0v,
       const __half* __restrict__ W2, const float* __restrict__ b1v,
       const float* __restrict__ pg, const float* __restrict__ pb,
       const float* __restrict__ pm, const float* __restrict__ pv,
       const float* __restrict__ Wp2, const float* __restrict__ bp2,
       float* __restrict__ outf, int nrows) {
    extern __shared__ __half smh[];
    __half* At   = smh;
    __half* WsB0 = smh + AT_HALVES;
    __half* WsB1 = smh + AT_HALVES + WBUF;

    __shared__ float sSB0[HID], sS20[HID], sAD0[HID];
    __shared__ float sSB1[HID], sS21[HID], sAD1[HID];
    __shared__ float sWp[3 * HID];
    __shared__ float redF[192];

    const int tid  = threadIdx.x;
    const int lane = tid & 31;
    const int wid  = tid >> 5;
    const int rw   = wid & 1;
    const int cw   = wid >> 1;
    const int g    = lane >> 2;
    const int t4   = lane & 3;
    const int warpRow = rw * 32;
    const int cb   = cw * 48;
    const int rb   = blockIdx.x * 64;

    for (int c = tid; c < HID; c += 512) {
        float s2 = rsqrtf(pv[c] + BN_EPS) * pg[c];
        sSB0[c] = b0v[c];
        sS20[c] = s2;
        sAD0[c] = pb[c] - pm[c] * s2;
        float s2b = rsqrtf(pv[HID + c] + BN_EPS) * pg[HID + c];
        sSB1[c] = b1v[c];
        sS21[c] = s2b;
        sAD1[c] = pb[HID + c] - pm[HID + c] * s2b;
    }
    if (tid < 192) redF[tid] = 0.0f;
    for (int c = tid; c < 3 * HID; c += 512) sWp[c] = Wp2[c];

#pragma unroll
    for (int j = 0; j < 12; j++) {
        int idx = tid + j * 512;
        int r = idx / 96, c = idx % 96;
        uint2 v = make_uint2(0u, 0u);
        if (rb + r < nrows)
            v = *(const uint2*)(A1 + (size_t)(rb + r) * HID + c * 4);
        *(uint2*)&At[r * ASTR2 + c * 4] = v;
    }

    const int m8 = lane >> 3;
    const int r8 = lane & 7;
    uint32_t aBase[2], bAddr[2][3];
    {
        int rowi = (m8 & 1) * 8 + r8;
        int koffq = (m8 >> 1) * 8;
        int nrowi = (m8 >> 1) * 8 + r8;
        int nkoff = (m8 & 1) * 8;
#pragma unroll
        for (int mt = 0; mt < 2; mt++)
            aBase[mt] = smem_u32(&At[(warpRow + mt * 16 + rowi) * ASTR2 + koffq]);
#pragma unroll
        for (int p = 0; p < 3; p++) {
            int off = (cb + p * 16 + nrowi) * HSTR + nkoff;
            bAddr[0][p] = smem_u32(&WsB0[off]);
            bAddr[1][p] = smem_u32(&WsB1[off]);
        }
    }

    int wr_[3], wq_[3], wOff[3];
#pragma unroll
    for (int i = 0; i < 3; i++) {
        int idx = tid + i * 512;
        wr_[i] = idx >> 2;
        wq_[i] = idx & 3;
        wOff[i] = wr_[i] * HSTR + wq_[i] * 4;
    }

    float acc[2][6][4];
    uint2 wvP[3];

    for (int stage = 0; stage < 2; stage++) {
        const __half* W = stage ? W2 : W1;
#pragma unroll
        for (int mt = 0; mt < 2; mt++)
#pragma unroll
            for (int nt = 0; nt < 6; nt++)
#pragma unroll
                for (int q = 0; q < 4; q++) acc[mt][nt][q] = 0.0f;

#pragma unroll
        for (int i = 0; i < 3; i++) {
            wvP[i] = *(const uint2*)(W + (size_t)wr_[i] * HID + wq_[i] * 4);
            *(uint2*)&WsB0[wOff[i]] = wvP[i];
        }

        for (int it = 0; it < 24; it++) {
            const int b = it & 1;
            __syncthreads();

            if (it + 1 < 24) {
                const int k0 = (it + 1) * 16;
#pragma unroll
                for (int i = 0; i < 3; i++)
                    wvP[i] = *(const uint2*)(W + (size_t)wr_[i] * HID + k0 + wq_[i] * 4);
            }

            {
                const uint32_t ko = (uint32_t)(it * 32);
                uint32_t a[2][4];
                LDSM_X4(a[0][0], a[0][1], a[0][2], a[0][3], aBase[0] + ko);
                LDSM_X4(a[1][0], a[1][1], a[1][2], a[1][3], aBase[1] + ko);
                uint32_t bfr[12];
                LDSM_X4(bfr[0], bfr[1], bfr[2],  bfr[3],  bAddr[b][0]);
                LDSM_X4(bfr[4], bfr[5], bfr[6],  bfr[7],  bAddr[b][1]);
                LDSM_X4(bfr[8], bfr[9], bfr[10], bfr[11], bAddr[b][2]);
#pragma unroll
                for (int nt = 0; nt < 6; nt++) {
                    uint32_t b0 = bfr[nt * 2], b1 = bfr[nt * 2 + 1];
                    mma_f16(acc[0][nt], a[0][0], a[0][1], a[0][2], a[0][3], b0, b1);
                    mma_f16(acc[1][nt], a[1][0], a[1][1], a[1][2], a[1][3], b0, b1);
                }
            }

            if (it + 1 < 24) {
                __half* Wn = b ? WsB0 : WsB1;
#pragma unroll
                for (int i = 0; i < 3; i++)
                    *(uint2*)&Wn[wOff[i]] = wvP[i];
            }
        }
        __syncthreads();

        if (stage == 0) {
#pragma unroll
            for (int mt = 0; mt < 2; mt++) {
                int lr0 = warpRow + mt * 16 + g;
                int lr1 = lr0 + 8;
#pragma unroll
                for (int nt = 0; nt < 6; nt++) {
                    int col = cb + nt * 8 + 2 * t4;
                    float bb0 = sSB0[col], bb1 = sSB0[col + 1];
                    float m0 = sS20[col], m1 = sS20[col + 1];
                    float d0 = sAD0[col], d1 = sAD0[col + 1];
                    float x0 = fmaxf((acc[mt][nt][0] + bb0) * m0 + d0, 0.0f);
                    float x1 = fmaxf((acc[mt][nt][1] + bb1) * m1 + d1, 0.0f);
                    float x2 = fmaxf((acc[mt][nt][2] + bb0) * m0 + d0, 0.0f);
                    float x3 = fmaxf((acc[mt][nt][3] + bb1) * m1 + d1, 0.0f);
                    *(uint32_t*)&At[lr0 * ASTR2 + col] = h2pack(x0, x1);
                    *(uint32_t*)&At[lr1 * ASTR2 + col] = h2pack(x2, x3);
                }
            }
        }
    }

    {
        float p0[2][3], p1[2][3];
#pragma unroll
        for (int mt = 0; mt < 2; mt++)
#pragma unroll
            for (int o = 0; o < 3; o++) { p0[mt][o] = 0.0f; p1[mt][o] = 0.0f; }

#pragma unroll
        for (int mt = 0; mt < 2; mt++) {
#pragma unroll
            for (int nt = 0; nt < 6; nt++) {
                int col = cb + nt * 8 + 2 * t4;
                float bb0 = sSB1[col], bb1 = sSB1[col + 1];
                float m0 = sS21[col], m1 = sS21[col + 1];
                float d0 = sAD1[col], d1 = sAD1[col + 1];
                float x0 = fmaxf((acc[mt][nt][0] + bb0) * m0 + d0, 0.0f);
                float x1 = fmaxf((acc[mt][nt][1] + bb1) * m1 + d1, 0.0f);
                float x2 = fmaxf((acc[mt][nt][2] + bb0) * m0 + d0, 0.0f);
                float x3 = fmaxf((acc[mt][nt][3] + bb1) * m1 + d1, 0.0f);
#pragma unroll
                for (int o = 0; o < 3; o++) {
                    float w0 = sWp[o * HID + col], w1 = sWp[o * HID + col + 1];
                    p0[mt][o] = fmaf(x0, w0, fmaf(x1, w1, p0[mt][o]));
                    p1[mt][o] = fmaf(x2, w0, fmaf(x3, w1, p1[mt][o]));
                }
            }
        }
#pragma unroll
        for (int mt = 0; mt < 2; mt++)
#pragma unroll
            for (int o = 0; o < 3; o++) {
                float v0 = p0[mt][o], v1 = p1[mt][o];
                v0 += __shfl_xor_sync(0xFFFFFFFFu, v0, 1);
                v0 += __shfl_xor_sync(0xFFFFFFFFu, v0, 2);
                v1 += __shfl_xor_sync(0xFFFFFFFFu, v1, 1);
                v1 += __shfl_xor_sync(0xFFFFFFFFu, v1, 2);
                if (t4 == 0) {
                    atomicAdd(&redF[(warpRow + mt * 16 + g) * 3 + o], v0);
                    atomicAdd(&redF[(warpRow + mt * 16 + g + 8) * 3 + o], v1);
                }
            }
        __syncthreads();
        if (tid < 64) {
            int row = rb + tid;
            if (row < nrows) {
                outf[(size_t)row * 3 + 0] = redF[tid * 3 + 0] + bp2[0];
                outf[(size_t)row * 3 + 1] = redF[tid * 3 + 1] + bp2[1];
                outf[(size_t)row * 3 + 2] = redF[tid * 3 + 2] + bp2[2];
            }
        }
    }
}

// ---------------------------------------------------------------------------
extern "C" void kernel_launch(void* const* d_in, const int* in_sizes, int n_in,
                              void* d_out, int out_size) {
    const float* x    = (const float*)d_in[0];
    const int*   ei   = (const int*)  d_in[1];
    const float* Wl0  = (const float*)d_in[2];
    const float* bl0  = (const float*)d_in[3];
    const float* Wr0  = (const float*)d_in[4];
    const float* Wl   = (const float*)d_in[5];
    const float* bl   = (const float*)d_in[6];
    const float* Wr   = (const float*)d_in[7];
    const float* bng  = (const float*)d_in[8];
    const float* bnb  = (const float*)d_in[9];
    const float* bnm  = (const float*)d_in[10];
    const float* bnv  = (const float*)d_in[11];
    const float* Wp0  = (const float*)d_in[12];
    const float* bp0  = (const float*)d_in[13];
    const float* Wp1  = (const float*)d_in[14];
    const float* bp1  = (const float*)d_in[15];
    const float* Wp2  = (const float*)d_in[16];
    const float* bp2  = (const float*)d_in[17];
    const float* pg   = (const float*)d_in[18];
    const float* pb   = (const float*)d_in[19];
    const float* pm   = (const float*)d_in[20];
    const float* pv   = (const float*)d_in[21];

    const int* src = ei;
    const int* dst = ei + EE;

    __half *agg16, *shA, *shB, *wl16, *wr16, *wp016, *wp116;
    int *deg, *inc, *rowptr, *cur, *csrc, *bsum;
    cudaGetSymbolAddress((void**)&agg16,  g_agg16);
    cudaGetSymbolAddress((void**)&shA,    g_shA);
    cudaGetSymbolAddress((void**)&shB,    g_shB);
    cudaGetSymbolAddress((void**)&wl16,   g_wl16);
    cudaGetSymbolAddress((void**)&wr16,   g_wr16);
    cudaGetSymbolAddress((void**)&wp016,  g_wp016);
    cudaGetSymbolAddress((void**)&wp116,  g_wp116);
    cudaGetSymbolAddress((void**)&deg,    g_deg);
    cudaGetSymbolAddress((void**)&inc,    g_inc);
    cudaGetSymbolAddress((void**)&rowptr, g_rowptr);
    cudaGetSymbolAddress((void**)&cur,    g_cur);
    cudaGetSymbolAddress((void**)&csrc,   g_csrc);
    cudaGetSymbolAddress((void**)&bsum,   g_bsum);

    cudaFuncSetAttribute(k_mma,  cudaFuncAttributeMaxDynamicSharedMemorySize, MMA_DSMEM);
    cudaFuncSetAttribute(k_proj, cudaFuncAttributeMaxDynamicSharedMemorySize, PROJ_DSMEM);

    // ---- weight conversion (single launch) ----
    {
        int ntot = (4 * WMAT + 4 * WMAT + WMAT + WMAT) / 4;
        k_cvt_all<<<(ntot + 255) / 256, 256>>>(
            (const float4*)Wl, (const float4*)Wr, (const float4*)Wp0, (const float4*)Wp1,
            (uint2*)wl16, (uint2*)wr16, (uint2*)wp016, (uint2*)wp116);
    }

    // ---- CSR build ----
    cudaMemsetAsync(deg, 0, NN * sizeof(int));
    k_hist<<<(EE + 255) / 256, 256>>>(dst, deg, EE);
    k_scan_block<<<NSCANB, SCAN_B>>>(deg, inc, bsum, NN);
    k_scan_bsum<<<1, 128>>>(bsum, NSCANB);
    k_csr_fin<<<(NN + 255) / 256, 256>>>(deg, inc, bsum, rowptr, cur, NN);
    k_fill<<<(EE + 255) / 256, 256>>>(src, dst, cur, csrc, EE);

    // ---- layer 0 (K=10), fused CSR gather ----
    k_layer0<<<(NN + L0R - 1) / L0R, 384>>>(rowptr, csrc, x, Wl0, bl0, Wr0,
                                            bng, bnb, bnm, bnv, shA, NN);

    // ---- layers 1..4: fp16 gather + dual fp16 mma GEMM (BK=32) ----
    const int gblocks = (NN + 63) / 64;
    for (int t = 1; t < TT; t++) {
        k_gather384<<<(NN * 32 + 255) / 256, 256>>>(rowptr, csrc, shA, agg16, NN);
        k_mma<<<gblocks, 512, MMA_DSMEM>>>(
            agg16, wl16 + (size_t)(t - 1) * WMAT, bl + (t - 1) * HID,
            shA,   wr16 + (size_t)(t - 1) * WMAT,
            bng + t * HID, bnb + t * HID, bnm + t * HID, bnv + t * HID,
            shB, NN);
        __half* ts = shA; shA = shB; shB = ts;
    }

    // ---- fused projection MLP ----
    k_proj<<<gblocks, 512, PROJ_DSMEM>>>(shA, wp016, bp0, wp116, bp1,
                                         pg, pb, pm, pv, Wp2, bp2,
                                         (float*)d_out, NN);

    (void)in_sizes; (void)n_in; (void)out_size;
}

// round 15
// speedup vs baseline: 1.4641x; 1.2210x over previous
#include <cuda_runtime.h>
#include <cuda_fp16.h>
#include <math.h>
#include <cstdint>

#define NN 100000
#define EE 300000
#define IN_DIM 10
#define HID 384
#define TT 5
#define BN_EPS 1e-5f
#define WMAT (HID * HID)

#define SCAN_B 1024
#define NSCANB ((NN + SCAN_B - 1) / SCAN_B)   // 98

// Static scratch (allocation-free rule) — all activations fp16
__device__ __half  g_agg16[(size_t)NN * HID];
__device__ __half  g_shA [(size_t)NN * HID];
__device__ __half  g_shB [(size_t)NN * HID];
__device__ __half  g_wl16[4 * WMAT];
__device__ __half  g_wr16[4 * WMAT];
__device__ __half  g_wp016[WMAT];
__device__ __half  g_wp116[WMAT];
__device__ int   g_deg [NN];
__device__ int   g_inc [NN];
__device__ int   g_rowptr[NN + 1];
__device__ int   g_cur [NN];
__device__ int   g_csrc[EE];
__device__ int   g_bsum[128];

// ---------------------------------------------------------------------------
// helpers
// ---------------------------------------------------------------------------
__device__ __forceinline__ uint32_t smem_u32(const void* p) {
    uint32_t a;
    asm("{ .reg .u64 t; cvta.to.shared.u64 t, %1; cvt.u32.u64 %0, t; }" : "=r"(a) : "l"(p));
    return a;
}

__device__ __forceinline__ void mma_f16(float* c, uint32_t a0, uint32_t a1,
                                        uint32_t a2, uint32_t a3,
                                        uint32_t b0, uint32_t b1) {
    asm volatile("mma.sync.aligned.m16n8k16.row.col.f32.f16.f16.f32 "
                 "{%0,%1,%2,%3}, {%4,%5,%6,%7}, {%8,%9}, {%0,%1,%2,%3};"
                 : "+f"(c[0]), "+f"(c[1]), "+f"(c[2]), "+f"(c[3])
                 : "r"(a0), "r"(a1), "r"(a2), "r"(a3), "r"(b0), "r"(b1));
}

#define LDSM_X4(r0, r1, r2, r3, addr) \
    asm volatile("ldmatrix.sync.aligned.m8n8.x4.shared.b16 {%0,%1,%2,%3}, [%4];" \
                 : "=r"(r0), "=r"(r1), "=r"(r2), "=r"(r3) : "r"(addr))

#define CP16(dst, src) \
    asm volatile("cp.async.cg.shared.global [%0], [%1], 16;" :: "r"(dst), "l"(src))
#define CP16Z(dst, src, nbytes) \
    asm volatile("cp.async.cg.shared.global [%0], [%1], 16, %2;" :: "r"(dst), "l"(src), "r"(nbytes))
#define CP_COMMIT() asm volatile("cp.async.commit_group;" ::: "memory")
#define CP_WAIT0()  asm volatile("cp.async.wait_group 0;" ::: "memory")

__device__ __forceinline__ float elu_f(float v) {
    return (v > 0.0f) ? v : (__expf(v) - 1.0f);
}

__device__ __forceinline__ uint32_t h2pack(float x, float y) {
    __half2 h = __float22half2_rn(make_float2(x, y));
    return *(uint32_t*)&h;
}

// single fp32->fp16 conversion kernel covering all weight arrays
__global__ void k_cvt_all(const float4* __restrict__ wl, const float4* __restrict__ wr,
                          const float4* __restrict__ wp0, const float4* __restrict__ wp1,
                          uint2* __restrict__ owl, uint2* __restrict__ owr,
                          uint2* __restrict__ owp0, uint2* __restrict__ owp1) {
    const int n1 = 4 * WMAT / 4;
    const int n2 = n1 + 4 * WMAT / 4;
    const int n3 = n2 + WMAT / 4;
    const int n4 = n3 + WMAT / 4;
    int i = blockIdx.x * blockDim.x + threadIdx.x;
    if (i >= n4) return;
    const float4* s;
    uint2* d;
    int j;
    if (i < n1)      { s = wl;  d = owl;  j = i; }
    else if (i < n2) { s = wr;  d = owr;  j = i - n1; }
    else if (i < n3) { s = wp0; d = owp0; j = i - n2; }
    else             { s = wp1; d = owp1; j = i - n3; }
    float4 v = s[j];
    uint2 o;
    o.x = h2pack(v.x, v.y);
    o.y = h2pack(v.z, v.w);
    d[j] = o;
}

// ---------------------------------------------------------------------------
// CSR build
// ---------------------------------------------------------------------------
__global__ void k_hist(const int* __restrict__ dst, int* __restrict__ deg, int e) {
    int i = blockIdx.x * blockDim.x + threadIdx.x;
    if (i < e) atomicAdd(&deg[dst[i]], 1);
}

__global__ void k_scan_block(const int* __restrict__ deg, int* __restrict__ inc,
                             int* __restrict__ bsum, int n) {
    __shared__ int s[SCAN_B];
    int i = blockIdx.x * SCAN_B + threadIdx.x;
    s[threadIdx.x] = (i < n) ? deg[i] : 0;
    __syncthreads();
#pragma unroll
    for (int o = 1; o < SCAN_B; o <<= 1) {
        int t = (threadIdx.x >= o) ? s[threadIdx.x - o] : 0;
        __syncthreads();
        s[threadIdx.x] += t;
        __syncthreads();
    }
    if (i < n) inc[i] = s[threadIdx.x];
    if (threadIdx.x == SCAN_B - 1) bsum[blockIdx.x] = s[SCAN_B - 1];
}

__global__ void k_scan_bsum(int* __restrict__ bsum, int nb) {
    __shared__ int s[128];
    if (threadIdx.x < nb) s[threadIdx.x] = bsum[threadIdx.x];
    __syncthreads();
    if (threadIdx.x == 0) {
        int run = 0;
        for (int i = 0; i < nb; i++) { run += s[i]; s[i] = run; }
    }
    __syncthreads();
    if (threadIdx.x < nb) bsum[threadIdx.x] = s[threadIdx.x];
}

__global__ void k_csr_fin(const int* __restrict__ deg, const int* __restrict__ inc,
                          const int* __restrict__ bsum,
                          int* __restrict__ rowptr, int* __restrict__ cur, int n) {
    int i = blockIdx.x * blockDim.x + threadIdx.x;
    if (i >= n) return;
    int b = i / SCAN_B;
    int total = inc[i] + (b > 0 ? bsum[b - 1] : 0);
    rowptr[i + 1] = total;
    cur[i] = total - deg[i];
    if (i == 0) rowptr[0] = 0;
}

__global__ void k_fill(const int* __restrict__ src, const int* __restrict__ dst,
                       int* __restrict__ cur, int* __restrict__ csrc, int e) {
    int i = blockIdx.x * blockDim.x + threadIdx.x;
    if (i >= e) return;
    int pos = atomicAdd(&cur[dst[i]], 1);
    csrc[pos] = src[i];
}

// ---------------------------------------------------------------------------
// CSR mean-gather, width 384, fp16 in/out, fp32 accumulate, 2x unroll
// ---------------------------------------------------------------------------
__global__ void k_gather384(const int* __restrict__ rowptr, const int* __restrict__ csrc,
                            const __half* __restrict__ hs, __half* __restrict__ agg,
                            int n) {
    int node = (blockIdx.x * blockDim.x + threadIdx.x) >> 5;
    int lane = threadIdx.x & 31;
    if (node >= n) return;
    int beg = rowptr[node], end = rowptr[node + 1];
    float a[12], b[12];
#pragma unroll
    for (int i = 0; i < 12; i++) { a[i] = 0.0f; b[i] = 0.0f; }

    int e = beg;
    for (; e + 1 < end; e += 2) {
        int s0 = csrc[e], s1 = csrc[e + 1];
        const uint2* p0 = (const uint2*)(hs + (size_t)s0 * HID) + lane;
        const uint2* p1 = (const uint2*)(hs + (size_t)s1 * HID) + lane;
        uint2 u0 = p0[0], u1 = p0[32], u2 = p0[64];
        uint2 w0 = p1[0], w1 = p1[32], w2 = p1[64];
        float2 f;
        f = __half22float2(*(__half2*)&u0.x); a[0] += f.x; a[1] += f.y;
        f = __half22float2(*(__half2*)&u0.y); a[2] += f.x; a[3] += f.y;
        f = __half22float2(*(__half2*)&u1.x); a[4] += f.x; a[5] += f.y;
        f = __half22float2(*(__half2*)&u1.y); a[6] += f.x; a[7] += f.y;
        f = __half22float2(*(__half2*)&u2.x); a[8] += f.x; a[9] += f.y;
        f = __half22float2(*(__half2*)&u2.y); a[10] += f.x; a[11] += f.y;
        f = __half22float2(*(__half2*)&w0.x); b[0] += f.x; b[1] += f.y;
        f = __half22float2(*(__half2*)&w0.y); b[2] += f.x; b[3] += f.y;
        f = __half22float2(*(__half2*)&w1.x); b[4] += f.x; b[5] += f.y;
        f = __half22float2(*(__half2*)&w1.y); b[6] += f.x; b[7] += f.y;
        f = __half22float2(*(__half2*)&w2.x); b[8] += f.x; b[9] += f.y;
        f = __half22float2(*(__half2*)&w2.y); b[10] += f.x; b[11] += f.y;
    }
    if (e < end) {
        const uint2* p0 = (const uint2*)(hs + (size_t)csrc[e] * HID) + lane;
        uint2 u0 = p0[0], u1 = p0[32], u2 = p0[64];
        float2 f;
        f = __half22float2(*(__half2*)&u0.x); a[0] += f.x; a[1] += f.y;
        f = __half22float2(*(__half2*)&u0.y); a[2] += f.x; a[3] += f.y;
        f = __half22float2(*(__half2*)&u1.x); a[4] += f.x; a[5] += f.y;
        f = __half22float2(*(__half2*)&u1.y); a[6] += f.x; a[7] += f.y;
        f = __half22float2(*(__half2*)&u2.x); a[8] += f.x; a[9] += f.y;
        f = __half22float2(*(__half2*)&u2.y); a[10] += f.x; a[11] += f.y;
    }

    float iv = 1.0f / fmaxf((float)(end - beg), 1.0f);
    uint2* o = (uint2*)(agg + (size_t)node * HID) + lane;
    uint2 r;
    r.x = h2pack((a[0]+b[0])*iv, (a[1]+b[1])*iv);
    r.y = h2pack((a[2]+b[2])*iv, (a[3]+b[3])*iv);
    o[0] = r;
    r.x = h2pack((a[4]+b[4])*iv, (a[5]+b[5])*iv);
    r.y = h2pack((a[6]+b[6])*iv, (a[7]+b[7])*iv);
    o[32] = r;
    r.x = h2pack((a[8]+b[8])*iv, (a[9]+b[9])*iv);
    r.y = h2pack((a[10]+b[10])*iv, (a[11]+b[11])*iv);
    o[64] = r;
}

// ---------------------------------------------------------------------------
// Layer 0 SAGE: K=10, 32 rows/block, 384 threads; fused CSR mean-gather.
// ---------------------------------------------------------------------------
#define L0R 32
__global__ void k_layer0(const int* __restrict__ rowptr, const int* __restrict__ csrc,
                         const float* __restrict__ x,
                         const float* __restrict__ Wl, const float* __restrict__ bl,
                         const float* __restrict__ Wr,
                         const float* __restrict__ bng, const float* __restrict__ bnb,
                         const float* __restrict__ bnm, const float* __restrict__ bnv,
                         __half* __restrict__ hs, int n) {
    __shared__ float sA[L0R][IN_DIM];
    __shared__ float sX[L0R][IN_DIM];
    __shared__ float red[L0R];
    int t = threadIdx.x;
    int row0 = blockIdx.x * L0R;

    if (t < L0R * IN_DIM) {
        int r = t / IN_DIM, f = t % IN_DIM;
        int row = row0 + r;
        float a = 0.0f, xv = 0.0f;
        if (row < n) {
            xv = x[(size_t)row * IN_DIM + f];
            int beg = rowptr[row], end = rowptr[row + 1];
            for (int e = beg; e < end; e++)
                a += x[(size_t)csrc[e] * IN_DIM + f];
            a /= fmaxf((float)(end - beg), 1.0f);
        }
        sA[r][f] = a;
        sX[r][f] = xv;
    } else if (t < L0R * IN_DIM + L0R) {
        red[t - L0R * IN_DIM] = 0.0f;
    }
    __syncthreads();

    int j = t;
    float wl[IN_DIM], wr[IN_DIM];
#pragma unroll
    for (int k = 0; k < IN_DIM; k++) {
        wl[k] = Wl[j * IN_DIM + k];
        wr[k] = Wr[j * IN_DIM + k];
    }
    float bb = bl[j];

    float v[L0R];
#pragma unroll
    for (int r = 0; r < L0R; r++) {
        float s = bb;
#pragma unroll
        for (int k = 0; k < IN_DIM; k++)
            s += sA[r][k] * wl[k] + sX[r][k] * wr[k];
        v[r] = s;
    }

    int lane = t & 31;
#pragma unroll
    for (int r = 0; r < L0R; r++) {
        float p = v[r] * v[r];
#pragma unroll
        for (int o = 16; o > 0; o >>= 1) p += __shfl_xor_sync(0xFFFFFFFFu, p, o);
        if (lane == 0) atomicAdd(&red[r], p);
    }
    __syncthreads();

    float gm = bng[j], gb = bnb[j], mm = bnm[j], vv = bnv[j];
    float bscale = rsqrtf(vv + BN_EPS) * gm;
#pragma unroll
    for (int r = 0; r < L0R; r++) {
        int row = row0 + r;
        if (row >= n) continue;
        float sc = 1.0f / fmaxf(sqrtf(red[r]), 1e-12f);
        float val = elu_f((v[r] * sc - mm) * bscale + gb);
        hs[(size_t)row * HID + j] = __float2half(val);
    }
}

// ---------------------------------------------------------------------------
// Dual fp16 GEMM — BK=32, double-buffered, cp.async staging, 1 bar/iter.
//   C[64, 384] = A1*W1^T + A2*W2^T + bias ; L2-normalize row, BN, ELU -> fp16
// Row stride 40 halves (80B): ldmatrix conflict-free; 16B cp.async aligned.
// ---------------------------------------------------------------------------
#define KSTR 40
#define ABUF2 (64 * KSTR)                    // 2560 halves
#define WBUF2 (384 * KSTR)                   // 15360 halves
#define MMA_DSMEM ((2 * ABUF2 + 2 * WBUF2) * 2)   // 71680 B

__global__ void __launch_bounds__(512, 1)
k_mma(const __half* __restrict__ A1, const __half* __restrict__ W1,
      const float* __restrict__ bias,
      const __half* __restrict__ A2, const __half* __restrict__ W2,
      const float* __restrict__ bng, const float* __restrict__ bnb,
      const float* __restrict__ bnm, const float* __restrict__ bnv,
      __half* __restrict__ outh, int nrows) {
    extern __shared__ __half smh[];
    __half* AsB0 = smh;
    __half* AsB1 = smh + ABUF2;
    __half* WsB0 = smh + 2 * ABUF2;
    __half* WsB1 = smh + 2 * ABUF2 + WBUF2;

    __shared__ float sSB[HID], sS2[HID], sAD[HID];
    __shared__ float red[64];

    const int tid  = threadIdx.x;
    const int lane = tid & 31;
    const int wid  = tid >> 5;
    const int rw   = wid & 1;
    const int cw   = wid >> 1;
    const int g    = lane >> 2;
    const int t4   = lane & 3;
    const int warpRow = rw * 32;
    const int cb   = cw * 48;
    const int rb   = blockIdx.x * 64;

    for (int c = tid; c < HID; c += 512) {
        float s2 = rsqrtf(bnv[c] + BN_EPS) * bng[c];
        sSB[c] = bias[c];
        sS2[c] = s2;
        sAD[c] = bnb[c] - bnm[c] * s2;
    }
    if (tid < 64) red[tid] = 0.0f;

    // ldmatrix addresses
    const int m8 = lane >> 3;
    const int r8 = lane & 7;
    uint32_t aAddr[2][2], bAddr[2][3];
    {
        int rowi = (m8 & 1) * 8 + r8;
        int koff = (m8 >> 1) * 8;
        int nrowi = (m8 >> 1) * 8 + r8;
        int nkoff = (m8 & 1) * 8;
#pragma unroll
        for (int mt = 0; mt < 2; mt++) {
            int off = (warpRow + mt * 16 + rowi) * KSTR + koff;
            aAddr[0][mt] = smem_u32(&AsB0[off]);
            aAddr[1][mt] = smem_u32(&AsB1[off]);
        }
#pragma unroll
        for (int p = 0; p < 3; p++) {
            int off = (cb + p * 16 + nrowi) * KSTR + nkoff;
            bAddr[0][p] = smem_u32(&WsB0[off]);
            bAddr[1][p] = smem_u32(&WsB1[off]);
        }
    }

    // cp.async staging geometry: 16B chunks; A: 1/thread, W: 3/thread
    const int ar = tid >> 2, aq = tid & 3;         // A row 0..127? -> 64 rows x 4 chunks
    const int arow = tid >> 2;                      // 0..127 (only <64 valid via 512/4=128)
    const int aDstOff = (arow < 64 ? arow : 0) * KSTR * 2 + aq * 16;
    const bool aActive = (arow < 64);
    uint32_t aDst[2];
    aDst[0] = smem_u32(AsB0) + aDstOff;
    aDst[1] = smem_u32(AsB1) + aDstOff;
    int wrr[3], wqq[3];
    uint32_t wDst[2][3];
#pragma unroll
    for (int i = 0; i < 3; i++) {
        int idx = tid + i * 512;
        wrr[i] = idx >> 2;          // 0..383
        wqq[i] = idx & 3;           // 0..3
        int off = wrr[i] * KSTR * 2 + wqq[i] * 16;
        wDst[0][i] = smem_u32(WsB0) + off;
        wDst[1][i] = smem_u32(WsB1) + off;
    }

    const int S = 24;   // 2 passes x 12 iters (32 k per iter)

    float acc[2][6][4];
#pragma unroll
    for (int mt = 0; mt < 2; mt++)
#pragma unroll
        for (int nt = 0; nt < 6; nt++)
#pragma unroll
            for (int q = 0; q < 4; q++) acc[mt][nt][q] = 0.0f;

    // prologue: issue chunk 0 -> buf 0
    {
        if (aActive) {
            int row = rb + arow;
            const __half* srcp = A1 + (size_t)(row < nrows ? row : 0) * HID + aq * 8;
            CP16Z(aDst[0], srcp, (row < nrows) ? 16 : 0);
        }
#pragma unroll
        for (int i = 0; i < 3; i++)
            CP16(wDst[0][i], W1 + (size_t)wrr[i] * HID + wqq[i] * 8);
        CP_COMMIT();
    }

    for (int it = 0; it < S; it++) {
        const int b = it & 1;
        CP_WAIT0();
        __syncthreads();   // buf b data visible; all done reading buf b^1

        // issue chunk it+1 -> buf b^1
        if (it + 1 < S) {
            const int itn = it + 1;
            const int pass = itn / 12;
            const int k0 = (itn - pass * 12) * 32;
            const __half* A = pass ? A2 : A1;
            const __half* W = pass ? W2 : W1;
            if (aActive) {
                int row = rb + arow;
                const __half* srcp = A + (size_t)(row < nrows ? row : 0) * HID + k0 + aq * 8;
                CP16Z(aDst[b ^ 1], srcp, (row < nrows) ? 16 : 0);
            }
#pragma unroll
            for (int i = 0; i < 3; i++)
                CP16(wDst[b ^ 1][i], W + (size_t)wrr[i] * HID + k0 + wqq[i] * 8);
            CP_COMMIT();
        }

        // compute: 2 chunks x (5 ldmatrix + 12 MMA)
#pragma unroll
        for (int c = 0; c < 2; c++) {
            const uint32_t ko = (uint32_t)(c * 32);
            uint32_t a[2][4];
            LDSM_X4(a[0][0], a[0][1], a[0][2], a[0][3], aAddr[b][0] + ko);
            LDSM_X4(a[1][0], a[1][1], a[1][2], a[1][3], aAddr[b][1] + ko);
            uint32_t bfr[12];
            LDSM_X4(bfr[0], bfr[1], bfr[2],  bfr[3],  bAddr[b][0] + ko);
            LDSM_X4(bfr[4], bfr[5], bfr[6],  bfr[7],  bAddr[b][1] + ko);
            LDSM_X4(bfr[8], bfr[9], bfr[10], bfr[11], bAddr[b][2] + ko);
#pragma unroll
            for (int nt = 0; nt < 6; nt++) {
                uint32_t b0 = bfr[nt * 2], b1 = bfr[nt * 2 + 1];
                mma_f16(acc[0][nt], a[0][0], a[0][1], a[0][2], a[0][3], b0, b1);
                mma_f16(acc[1][nt], a[1][0], a[1][1], a[1][2], a[1][3], b0, b1);
            }
        }
    }
    __syncthreads();

    // epilogue: bias, L2 norm, BN, ELU
#pragma unroll
    for (int nt = 0; nt < 6; nt++) {
        int col = cb + nt * 8 + 2 * t4;
        float b0 = sSB[col], b1 = sSB[col + 1];
#pragma unroll
        for (int mt = 0; mt < 2; mt++) {
            acc[mt][nt][0] += b0; acc[mt][nt][1] += b1;
            acc[mt][nt][2] += b0; acc[mt][nt][3] += b1;
        }
    }
#pragma unroll
    for (int mt = 0; mt < 2; mt++) {
        float s0 = 0.0f, s1 = 0.0f;
#pragma unroll
        for (int nt = 0; nt < 6; nt++) {
            s0 = fmaf(acc[mt][nt][0], acc[mt][nt][0], s0);
            s0 = fmaf(acc[mt][nt][1], acc[mt][nt][1], s0);
            s1 = fmaf(acc[mt][nt][2], acc[mt][nt][2], s1);
            s1 = fmaf(acc[mt][nt][3], acc[mt][nt][3], s1);
        }
        s0 += __shfl_xor_sync(0xFFFFFFFFu, s0, 1);
        s0 += __shfl_xor_sync(0xFFFFFFFFu, s0, 2);
        s1 += __shfl_xor_sync(0xFFFFFFFFu, s1, 1);
        s1 += __shfl_xor_sync(0xFFFFFFFFu, s1, 2);
        if (t4 == 0) {
            atomicAdd(&red[warpRow + mt * 16 + g], s0);
            atomicAdd(&red[warpRow + mt * 16 + g + 8], s1);
        }
    }
    __syncthreads();
    float sc0[2], sc1[2];
#pragma unroll
    for (int mt = 0; mt < 2; mt++) {
        sc0[mt] = 1.0f / fmaxf(sqrtf(red[warpRow + mt * 16 + g]), 1e-12f);
        sc1[mt] = 1.0f / fmaxf(sqrtf(red[warpRow + mt * 16 + g + 8]), 1e-12f);
    }

#pragma unroll
    for (int mt = 0; mt < 2; mt++) {
        int row0 = rb + warpRow + mt * 16 + g;
        int row1 = row0 + 8;
        bool v0r = (row0 < nrows), v1r = (row1 < nrows);
#pragma unroll
        for (int nt = 0; nt < 6; nt++) {
            int col = cb + nt * 8 + 2 * t4;
            float m0 = sS2[col], m1 = sS2[col + 1];
            float d0 = sAD[col], d1 = sAD[col + 1];
            float x0 = elu_f(acc[mt][nt][0] * sc0[mt] * m0 + d0);
            float x1 = elu_f(acc[mt][nt][1] * sc0[mt] * m1 + d1);
            float x2 = elu_f(acc[mt][nt][2] * sc1[mt] * m0 + d0);
            float x3 = elu_f(acc[mt][nt][3] * sc1[mt] * m1 + d1);
            if (v0r) *(uint32_t*)(outh + (size_t)row0 * HID + col) = h2pack(x0, x1);
            if (v1r) *(uint32_t*)(outh + (size_t)row1 * HID + col) = h2pack(x2, x3);
        }
    }
}

// ---------------------------------------------------------------------------
// Fused projection MLP — BK=32 W staging (mirror of k_mma), persistent A tile.
// h1 = relu(bn0(A@Wp0^T+bp0)) in SMEM; h2 = relu(bn1(h1@Wp1^T+bp1));
// out = h2@Wp2^T + bp2.
// ---------------------------------------------------------------------------
#define ASTR2 392
#define AT_HALVES (64 * ASTR2)
#define PROJ_DSMEM ((AT_HALVES + 2 * WBUF2) * 2)   // 111616 B

__global__ void __launch_bounds__(512, 1)
k_proj(const __half* __restrict__ A1,
       const __half* __restrict__ W1, const float* __restrict__ b0v,
       const __half* __restrict__ W2, const float* __restrict__ b1v,
       const float* __restrict__ pg, const float* __restrict__ pb,
       const float* __restrict__ pm, const float* __restrict__ pv,
       const float* __restrict__ Wp2, const float* __restrict__ bp2,
       float* __restrict__ outf, int nrows) {
    extern __shared__ __half smh[];
    __half* At   = smh;
    __half* WsB0 = smh + AT_HALVES;
    __half* WsB1 = smh + AT_HALVES + WBUF2;

    __shared__ float sSB0[HID], sS20[HID], sAD0[HID];
    __shared__ float sSB1[HID], sS21[HID], sAD1[HID];
    __shared__ float sWp[3 * HID];
    __shared__ float redF[192];

    const int tid  = threadIdx.x;
    const int lane = tid & 31;
    const int wid  = tid >> 5;
    const int rw   = wid & 1;
    const int cw   = wid >> 1;
    const int g    = lane >> 2;
    const int t4   = lane & 3;
    const int warpRow = rw * 32;
    const int cb   = cw * 48;
    const int rb   = blockIdx.x * 64;

    for (int c = tid; c < HID; c += 512) {
        float s2 = rsqrtf(pv[c] + BN_EPS) * pg[c];
        sSB0[c] = b0v[c];
        sS20[c] = s2;
        sAD0[c] = pb[c] - pm[c] * s2;
        float s2b = rsqrtf(pv[HID + c] + BN_EPS) * pg[HID + c];
        sSB1[c] = b1v[c];
        sS21[c] = s2b;
        sAD1[c] = pb[HID + c] - pm[HID + c] * s2b;
    }
    if (tid < 192) redF[tid] = 0.0f;
    for (int c = tid; c < 3 * HID; c += 512) sWp[c] = Wp2[c];

#pragma unroll
    for (int j = 0; j < 12; j++) {
        int idx = tid + j * 512;
        int r = idx / 96, c = idx % 96;
        uint2 v = make_uint2(0u, 0u);
        if (rb + r < nrows)
            v = *(const uint2*)(A1 + (size_t)(rb + r) * HID + c * 4);
        *(uint2*)&At[r * ASTR2 + c * 4] = v;
    }

    const int m8 = lane >> 3;
    const int r8 = lane & 7;
    uint32_t aBase[2], bAddr[2][3];
    {
        int rowi = (m8 & 1) * 8 + r8;
        int koffq = (m8 >> 1) * 8;
        int nrowi = (m8 >> 1) * 8 + r8;
        int nkoff = (m8 & 1) * 8;
#pragma unroll
        for (int mt = 0; mt < 2; mt++)
            aBase[mt] = smem_u32(&At[(warpRow + mt * 16 + rowi) * ASTR2 + koffq]);
#pragma unroll
        for (int p = 0; p < 3; p++) {
            int off = (cb + p * 16 + nrowi) * KSTR + nkoff;
            bAddr[0][p] = smem_u32(&WsB0[off]);
            bAddr[1][p] = smem_u32(&WsB1[off]);
        }
    }

    // W staging (LDG path, 6 uint2/thread, KSTR layout)
    int wr_[6], wq_[6], wOff[6];
#pragma unroll
    for (int i = 0; i < 6; i++) {
        int idx = tid + i * 512;
        wr_[i] = idx >> 3;
        wq_[i] = idx & 7;
        wOff[i] = wr_[i] * KSTR + wq_[i] * 4;
    }

    float acc[2][6][4];
    uint2 wvP[6];

    for (int stage = 0; stage < 2; stage++) {
        const __half* W = stage ? W2 : W1;
#pragma unroll
        for (int mt = 0; mt < 2; mt++)
#pragma unroll
            for (int nt = 0; nt < 6; nt++)
#pragma unroll
                for (int q = 0; q < 4; q++) acc[mt][nt][q] = 0.0f;

        // prologue: chunk 0 -> buf 0
#pragma unroll
        for (int i = 0; i < 6; i++) {
            wvP[i] = *(const uint2*)(W + (size_t)wr_[i] * HID + wq_[i] * 4);
            *(uint2*)&WsB0[wOff[i]] = wvP[i];
        }

        for (int it = 0; it < 12; it++) {
            const int b = it & 1;
            __syncthreads();

            if (it + 1 < 12) {
                const int k0 = (it + 1) * 32;
#pragma unroll
                for (int i = 0; i < 6; i++)
                    wvP[i] = *(const uint2*)(W + (size_t)wr_[i] * HID + k0 + wq_[i] * 4);
            }

#pragma unroll
            for (int c = 0; c < 2; c++) {
                const uint32_t kA = (uint32_t)(it * 64 + c * 32);
                const uint32_t kW = (uint32_t)(c * 32);
                uint32_t a[2][4];
                LDSM_X4(a[0][0], a[0][1], a[0][2], a[0][3], aBase[0] + kA);
                LDSM_X4(a[1][0], a[1][1], a[1][2], a[1][3], aBase[1] + kA);
                uint32_t bfr[12];
                LDSM_X4(bfr[0], bfr[1], bfr[2],  bfr[3],  bAddr[b][0] + kW);
                LDSM_X4(bfr[4], bfr[5], bfr[6],  bfr[7],  bAddr[b][1] + kW);
                LDSM_X4(bfr[8], bfr[9], bfr[10], bfr[11], bAddr[b][2] + kW);
#pragma unroll
                for (int nt = 0; nt < 6; nt++) {
                    uint32_t b0 = bfr[nt * 2], b1 = bfr[nt * 2 + 1];
                    mma_f16(acc[0][nt], a[0][0], a[0][1], a[0][2], a[0][3], b0, b1);
                    mma_f16(acc[1][nt], a[1][0], a[1][1], a[1][2], a[1][3], b0, b1);
                }
            }

            if (it + 1 < 12) {
                __half* Wn = b ? WsB0 : WsB1;
#pragma unroll
                for (int i = 0; i < 6; i++)
                    *(uint2*)&Wn[wOff[i]] = wvP[i];
            }
        }
        __syncthreads();

        if (stage == 0) {
#pragma unroll
            for (int mt = 0; mt < 2; mt++) {
                int lr0 = warpRow + mt * 16 + g;
                int lr1 = lr0 + 8;
#pragma unroll
                for (int nt = 0; nt < 6; nt++) {
                    int col = cb + nt * 8 + 2 * t4;
                    float bb0 = sSB0[col], bb1 = sSB0[col + 1];
                    float m0 = sS20[col], m1 = sS20[col + 1];
                    float d0 = sAD0[col], d1 = sAD0[col + 1];
                    float x0 = fmaxf((acc[mt][nt][0] + bb0) * m0 + d0, 0.0f);
                    float x1 = fmaxf((acc[mt][nt][1] + bb1) * m1 + d1, 0.0f);
                    float x2 = fmaxf((acc[mt][nt][2] + bb0) * m0 + d0, 0.0f);
                    float x3 = fmaxf((acc[mt][nt][3] + bb1) * m1 + d1, 0.0f);
                    *(uint32_t*)&At[lr0 * ASTR2 + col] = h2pack(x0, x1);
                    *(uint32_t*)&At[lr1 * ASTR2 + col] = h2pack(x2, x3);
                }
            }
        }
    }

    {
        float p0[2][3], p1[2][3];
#pragma unroll
        for (int mt = 0; mt < 2; mt++)
#pragma unroll
            for (int o = 0; o < 3; o++) { p0[mt][o] = 0.0f; p1[mt][o] = 0.0f; }

#pragma unroll
        for (int mt = 0; mt < 2; mt++) {
#pragma unroll
            for (int nt = 0; nt < 6; nt++) {
                int col = cb + nt * 8 + 2 * t4;
                float bb0 = sSB1[col], bb1 = sSB1[col + 1];
                float m0 = sS21[col], m1 = sS21[col + 1];
                float d0 = sAD1[col], d1 = sAD1[col + 1];
                float x0 = fmaxf((acc[mt][nt][0] + bb0) * m0 + d0, 0.0f);
                float x1 = fmaxf((acc[mt][nt][1] + bb1) * m1 + d1, 0.0f);
                float x2 = fmaxf((acc[mt][nt][2] + bb0) * m0 + d0, 0.0f);
                float x3 = fmaxf((acc[mt][nt][3] + bb1) * m1 + d1, 0.0f);
#pragma unroll
                for (int o = 0; o < 3; o++) {
                    float w0 = sWp[o * HID + col], w1 = sWp[o * HID + col + 1];
                    p0[mt][o] = fmaf(x0, w0, fmaf(x1, w1, p0[mt][o]));
                    p1[mt][o] = fmaf(x2, w0, fmaf(x3, w1, p1[mt][o]));
                }
            }
        }
#pragma unroll
        for (int mt = 0; mt < 2; mt++)
#pragma unroll
            for (int o = 0; o < 3; o++) {
                float v0 = p0[mt][o], v1 = p1[mt][o];
                v0 += __shfl_xor_sync(0xFFFFFFFFu, v0, 1);
                v0 += __shfl_xor_sync(0xFFFFFFFFu, v0, 2);
                v1 += __shfl_xor_sync(0xFFFFFFFFu, v1, 1);
                v1 += __shfl_xor_sync(0xFFFFFFFFu, v1, 2);
                if (t4 == 0) {
                    atomicAdd(&redF[(warpRow + mt * 16 + g) * 3 + o], v0);
                    atomicAdd(&redF[(warpRow + mt * 16 + g + 8) * 3 + o], v1);
                }
            }
        __syncthreads();
        if (tid < 64) {
            int row = rb + tid;
            if (row < nrows) {
                outf[(size_t)row * 3 + 0] = redF[tid * 3 + 0] + bp2[0];
                outf[(size_t)row * 3 + 1] = redF[tid * 3 + 1] + bp2[1];
                outf[(size_t)row * 3 + 2] = redF[tid * 3 + 2] + bp2[2];
            }
        }
    }
}

// ---------------------------------------------------------------------------
extern "C" void kernel_launch(void* const* d_in, const int* in_sizes, int n_in,
                              void* d_out, int out_size) {
    const float* x    = (const float*)d_in[0];
    const int*   ei   = (const int*)  d_in[1];
    const float* Wl0  = (const float*)d_in[2];
    const float* bl0  = (const float*)d_in[3];
    const float* Wr0  = (const float*)d_in[4];
    const float* Wl   = (const float*)d_in[5];
    const float* bl   = (const float*)d_in[6];
    const float* Wr   = (const float*)d_in[7];
    const float* bng  = (const float*)d_in[8];
    const float* bnb  = (const float*)d_in[9];
    const float* bnm  = (const float*)d_in[10];
    const float* bnv  = (const float*)d_in[11];
    const float* Wp0  = (const float*)d_in[12];
    const float* bp0  = (const float*)d_in[13];
    const float* Wp1  = (const float*)d_in[14];
    const float* bp1  = (const float*)d_in[15];
    const float* Wp2  = (const float*)d_in[16];
    const float* bp2  = (const float*)d_in[17];
    const float* pg   = (const float*)d_in[18];
    const float* pb   = (const float*)d_in[19];
    const float* pm   = (const float*)d_in[20];
    const float* pv   = (const float*)d_in[21];

    const int* src = ei;
    const int* dst = ei + EE;

    __half *agg16, *shA, *shB, *wl16, *wr16, *wp016, *wp116;
    int *deg, *inc, *rowptr, *cur, *csrc, *bsum;
    cudaGetSymbolAddress((void**)&agg16,  g_agg16);
    cudaGetSymbolAddress((void**)&shA,    g_shA);
    cudaGetSymbolAddress((void**)&shB,    g_shB);
    cudaGetSymbolAddress((void**)&wl16,   g_wl16);
    cudaGetSymbolAddress((void**)&wr16,   g_wr16);
    cudaGetSymbolAddress((void**)&wp016,  g_wp016);
    cudaGetSymbolAddress((void**)&wp116,  g_wp116);
    cudaGetSymbolAddress((void**)&deg,    g_deg);
    cudaGetSymbolAddress((void**)&inc,    g_inc);
    cudaGetSymbolAddress((void**)&rowptr, g_rowptr);
    cudaGetSymbolAddress((void**)&cur,    g_cur);
    cudaGetSymbolAddress((void**)&csrc,   g_csrc);
    cudaGetSymbolAddress((void**)&bsum,   g_bsum);

    cudaFuncSetAttribute(k_mma,  cudaFuncAttributeMaxDynamicSharedMemorySize, MMA_DSMEM);
    cudaFuncSetAttribute(k_proj, cudaFuncAttributeMaxDynamicSharedMemorySize, PROJ_DSMEM);

    // ---- weight conversion (single launch) ----
    {
        int ntot = (4 * WMAT + 4 * WMAT + WMAT + WMAT) / 4;
        k_cvt_all<<<(ntot + 255) / 256, 256>>>(
            (const float4*)Wl, (const float4*)Wr, (const float4*)Wp0, (const float4*)Wp1,
            (uint2*)wl16, (uint2*)wr16, (uint2*)wp016, (uint2*)wp116);
    }

    // ---- CSR build ----
    cudaMemsetAsync(deg, 0, NN * sizeof(int));
    k_hist<<<(EE + 255) / 256, 256>>>(dst, deg, EE);
    k_scan_block<<<NSCANB, SCAN_B>>>(deg, inc, bsum, NN);
    k_scan_bsum<<<1, 128>>>(bsum, NSCANB);
    k_csr_fin<<<(NN + 255) / 256, 256>>>(deg, inc, bsum, rowptr, cur, NN);
    k_fill<<<(EE + 255) / 256, 256>>>(src, dst, cur, csrc, EE);

    // ---- layer 0 (K=10), fused CSR gather ----
    k_layer0<<<(NN + L0R - 1) / L0R, 384>>>(rowptr, csrc, x, Wl0, bl0, Wr0,
                                            bng, bnb, bnm, bnv, shA, NN);

    // ---- layers 1..4: fp16 gather + dual fp16 mma GEMM (cp.async) ----
    const int gblocks = (NN + 63) / 64;
    for (int t = 1; t < TT; t++) {
        k_gather384<<<(NN * 32 + 255) / 256, 256>>>(rowptr, csrc, shA, agg16, NN);
        k_mma<<<gblocks, 512, MMA_DSMEM>>>(
            agg16, wl16 + (size_t)(t - 1) * WMAT, bl + (t - 1) * HID,
            shA,   wr16 + (size_t)(t - 1) * WMAT,
            bng + t * HID, bnb + t * HID, bnm + t * HID, bnv + t * HID,
            shB, NN);
        __half* ts = shA; shA = shB; shB = ts;
    }

    // ---- fused projection MLP (BK=32) ----
    k_proj<<<gblocks, 512, PROJ_DSMEM>>>(shA, wp016, bp0, wp116, bp1,
                                         pg, pb, pm, pv, Wp2, bp2,
                                         (float*)d_out, NN);

    (void)in_sizes; (void)n_in; (void)out_size;
}